// round 13
// baseline (speedup 1.0000x reference)
#include <cuda_runtime.h>
#include <cuda_bf16.h>
#include <math.h>

// Shapes (fixed): N=64, T=300, V=25, C=64, K=3, F=64, I=16, d=T*I=4800
#define SCALE_D 0.014433756729740645f   // 1/sqrt(4800)

typedef unsigned long long u64;

__device__ __forceinline__ u64 pk2(float lo, float hi) {
    u64 r; asm("mov.b64 %0, {%1, %2};" : "=l"(r) : "f"(lo), "f"(hi)); return r;
}
__device__ __forceinline__ void up2(u64 v, float& a, float& b) {
    asm("mov.b64 {%0, %1}, %2;" : "=f"(a), "=f"(b) : "l"(v));
}
__device__ __forceinline__ void fma2(u64& d, u64 a, u64 b) {
    asm("fma.rn.f32x2 %0, %1, %2, %0;" : "+l"(d) : "l"(a), "l"(b));
}

__device__ __forceinline__ void ldsm_x4(unsigned& r0, unsigned& r1, unsigned& r2, unsigned& r3, unsigned addr) {
    asm volatile("ldmatrix.sync.aligned.m8n8.x4.shared.b16 {%0,%1,%2,%3}, [%4];"
                 : "=r"(r0), "=r"(r1), "=r"(r2), "=r"(r3) : "r"(addr));
}
__device__ __forceinline__ void ldsm_x2(unsigned& r0, unsigned& r1, unsigned addr) {
    asm volatile("ldmatrix.sync.aligned.m8n8.x2.shared.b16 {%0,%1}, [%2];"
                 : "=r"(r0), "=r"(r1) : "r"(addr));
}
__device__ __forceinline__ void ldsm_x4t(unsigned& r0, unsigned& r1, unsigned& r2, unsigned& r3, unsigned addr) {
    asm volatile("ldmatrix.sync.aligned.m8n8.x4.trans.shared.b16 {%0,%1,%2,%3}, [%4];"
                 : "=r"(r0), "=r"(r1), "=r"(r2), "=r"(r3) : "r"(addr));
}
__device__ __forceinline__ void mma_bf16(float* c, const unsigned* a, unsigned b0, unsigned b1) {
    asm volatile("mma.sync.aligned.m16n8k16.row.col.f32.bf16.bf16.f32 "
                 "{%0,%1,%2,%3}, {%4,%5,%6,%7}, {%8,%9}, {%0,%1,%2,%3};"
                 : "+f"(c[0]), "+f"(c[1]), "+f"(c[2]), "+f"(c[3])
                 : "r"(a[0]), "r"(a[1]), "r"(a[2]), "r"(a[3]), "r"(b0), "r"(b1));
}

// Scratch (module-static device memory; no runtime allocation)
__device__ float g_Spart[30 * 3 * 64 * 625];   // [chunk][k][n][v*25+w] partial scores
__device__ float g_Aad[3 * 64 * 625];          // A_adapt [k][n][v*25+w]

// ---------------------------------------------------------------------------
// Kernel 1: attention scores, FULLY tensor-core.
// Grid (30, 64), 256 threads. Per step: X -> bf16 hi/lo; E = X*[Wq|Wk] on mma;
// fragments + bias -> bf16 hi/lo Q/K (row-major [32][16], stride 24);
// S_k += Q K^T on mma (24 tiles, 3/warp, fp32 accs persist over 10 t's).
// ---------------------------------------------------------------------------
// smem byte offsets (score kernel)
#define SC_GHI   0            // bf16 [64][104]  13312 B
#define SC_GLO   13312        // 13312 B
#define SC_XH    26624        // bf16 [64][72]    9216 B
#define SC_XL    35840        //                  9216 B
#define SC_QH    45056        // bf16 [2][3][32][24] 9216 B
#define SC_QL    54272
#define SC_KH    63488
#define SC_KL    72704
#define SC_BS    81920        // f32 [96]          384 B
#define SC_TOTAL 82304

__global__ __launch_bounds__(256) void score_kernel(
    const float* __restrict__ x,
    const float* __restrict__ Wq, const float* __restrict__ bq,
    const float* __restrict__ Wk, const float* __restrict__ bk)
{
    extern __shared__ char smraw[];
    __nv_bfloat16* Ghi = (__nv_bfloat16*)(smraw + SC_GHI);
    __nv_bfloat16* Glo = (__nv_bfloat16*)(smraw + SC_GLO);
    __nv_bfloat16* Xh  = (__nv_bfloat16*)(smraw + SC_XH);
    __nv_bfloat16* Xl  = (__nv_bfloat16*)(smraw + SC_XL);
    __nv_bfloat16* Qh  = (__nv_bfloat16*)(smraw + SC_QH);
    __nv_bfloat16* Ql  = (__nv_bfloat16*)(smraw + SC_QL);
    __nv_bfloat16* Kh  = (__nv_bfloat16*)(smraw + SC_KH);
    __nv_bfloat16* Kl  = (__nv_bfloat16*)(smraw + SC_KL);
    float* bs = (float*)(smraw + SC_BS);

    const int tid = threadIdx.x;
    const int lane = tid & 31;
    const int wid = tid >> 5;
    const int chunk = blockIdx.x;
    const int n = blockIdx.y;

    // --- G = [Wq|Wk] -> bf16 hi/lo, row-major [c=64][j=96], stride 104 ---
    for (int e = tid; e < 6144; e += 256) {
        int c = e / 96, j = e % 96;
        float v;
        if (j < 48)  v = Wq[(j >> 4) * 1024 + c * 16 + (j & 15)];
        else { int jj = j - 48; v = Wk[(jj >> 4) * 1024 + c * 16 + (jj & 15)]; }
        __nv_bfloat16 hi = __float2bfloat16_rn(v);
        Ghi[c * 104 + j] = hi;
        Glo[c * 104 + j] = __float2bfloat16_rn(v - __bfloat162float(hi));
    }
    if (tid < 96) bs[tid] = (tid < 48) ? bq[tid] : bk[tid - 48];
    // zero X pad rows 50..63 (hi+lo)
    for (int e = tid; e < 1008; e += 256) {
        int r = 50 + e / 72, c = e % 72;
        Xh[r * 72 + c] = __float2bfloat16_rn(0.f);
        Xl[r * 72 + c] = __float2bfloat16_rn(0.f);
    }

    const float* xn = x + (n * 300 + chunk * 10) * 1600;

    // --- embedding mma decode: mt = wid>>1, chunks (wid&1)+2*c3 ---
    const int mt = wid >> 1;
    const int ncb = wid & 1;
    const int arow = mt * 16 + (lane & 15);
    const unsigned aoff = (unsigned)(arow * 144 + (lane >> 4) * 16);
    const unsigned boff = (unsigned)((lane & 15) * 208 + (lane >> 4) * 16);
    const unsigned xhB = (unsigned)__cvta_generic_to_shared(Xh);
    const unsigned xlB = (unsigned)__cvta_generic_to_shared(Xl);
    const unsigned ghB = (unsigned)__cvta_generic_to_shared(Ghi);
    const unsigned glB = (unsigned)__cvta_generic_to_shared(Glo);
    const int crow = mt * 16 + (lane >> 2);
    const int ccol = 2 * (lane & 3);

    // --- score mma decode: 3 tiles per warp, tau = wid*3 + j ---
    // tau: kq = tau>>3, tl = tau&7, smt = tl>>2, snt = tl&3
    const unsigned qhB = (unsigned)__cvta_generic_to_shared(Qh);
    const unsigned qlB = (unsigned)__cvta_generic_to_shared(Ql);
    const unsigned khB = (unsigned)__cvta_generic_to_shared(Kh);
    const unsigned klB = (unsigned)__cvta_generic_to_shared(Kl);
    int skq[3], smt[3], snt[3];
#pragma unroll
    for (int j = 0; j < 3; ++j) {
        int tau = wid * 3 + j;
        skq[j] = tau >> 3;
        smt[j] = (tau & 7) >> 2;
        snt[j] = tau & 3;
    }
    // per-lane address pieces (block = (ti*3+kq)*1536 bytes; row stride 48 B)
    const unsigned sa_row = (unsigned)((lane & 15) * 48 + (lane >> 4) * 16);
    const unsigned sb_row = (unsigned)((lane & 7) * 48 + ((lane >> 3) & 1) * 16);

    float S[3][4];
#pragma unroll
    for (int j = 0; j < 3; ++j)
#pragma unroll
        for (int q = 0; q < 4; ++q) S[j][q] = 0.f;

    for (int step = 0; step < 5; ++step) {
        __syncthreads();
        {   // convert 2 t-tiles of X -> bf16 hi/lo, rows 0-49
            const float4* src = (const float4*)(xn + step * 3200);
            for (int e = tid; e < 800; e += 256) {
                float4 v = src[e];
                int r = e >> 4, c = (e & 15) * 4;
                __nv_bfloat16 h0 = __float2bfloat16_rn(v.x), h1 = __float2bfloat16_rn(v.y);
                __nv_bfloat16 h2 = __float2bfloat16_rn(v.z), h3 = __float2bfloat16_rn(v.w);
                Xh[r * 72 + c]     = h0; Xh[r * 72 + c + 1] = h1;
                Xh[r * 72 + c + 2] = h2; Xh[r * 72 + c + 3] = h3;
                Xl[r * 72 + c]     = __float2bfloat16_rn(v.x - __bfloat162float(h0));
                Xl[r * 72 + c + 1] = __float2bfloat16_rn(v.y - __bfloat162float(h1));
                Xl[r * 72 + c + 2] = __float2bfloat16_rn(v.z - __bfloat162float(h2));
                Xl[r * 72 + c + 3] = __float2bfloat16_rn(v.w - __bfloat162float(h3));
            }
        }
        __syncthreads();

        // --- E = X * G on tensor cores; fragments -> bf16 Q/K hi/lo ---
        {
            float acc[6][4];
#pragma unroll
            for (int i = 0; i < 6; ++i)
#pragma unroll
                for (int j = 0; j < 4; ++j) acc[i][j] = 0.f;

#pragma unroll
            for (int ks = 0; ks < 4; ++ks) {
                unsigned ahi[4], alo[4];
                ldsm_x4(ahi[0], ahi[1], ahi[2], ahi[3], xhB + aoff + ks * 32);
                ldsm_x4(alo[0], alo[1], alo[2], alo[3], xlB + aoff + ks * 32);
#pragma unroll
                for (int c3 = 0; c3 < 3; ++c3) {
                    const int ch = ncb + 2 * c3;
                    const unsigned kb = boff + (unsigned)(ks * 3328 + ch * 32);
                    unsigned bh[4], bl[4];
                    ldsm_x4t(bh[0], bh[1], bh[2], bh[3], ghB + kb);
                    ldsm_x4t(bl[0], bl[1], bl[2], bl[3], glB + kb);
                    float* a0 = acc[c3 * 2];
                    float* a1 = acc[c3 * 2 + 1];
                    mma_bf16(a0, ahi, bh[0], bh[1]);
                    mma_bf16(a0, ahi, bl[0], bl[1]);
                    mma_bf16(a0, alo, bh[0], bh[1]);
                    mma_bf16(a1, ahi, bh[2], bh[3]);
                    mma_bf16(a1, ahi, bl[2], bl[3]);
                    mma_bf16(a1, alo, bh[2], bh[3]);
                }
            }
            // fragments + bias -> bf16 hi/lo, row-major Q/K [ti][kq][32 v][24]
#pragma unroll
            for (int c3 = 0; c3 < 3; ++c3) {
                const int ch = ncb + 2 * c3;
#pragma unroll
                for (int nt = 0; nt < 2; ++nt) {
                    const float* a = acc[c3 * 2 + nt];
                    const int col0 = ch * 16 + nt * 8 + ccol;
#pragma unroll
                    for (int rr = 0; rr < 2; ++rr) {
                        const int r = crow + rr * 8;
                        if (r < 50) {
                            const int t2 = (r >= 25);
                            const int v = r - t2 * 25;
#pragma unroll
                            for (int jj = 0; jj < 2; ++jj) {
                                const int j = col0 + jj;
                                const float val = a[rr * 2 + jj] + bs[j];
                                const int qk = (j >= 48);
                                const int jl = j - qk * 48;
                                const int idx = ((t2 * 3 + (jl >> 4)) * 32 + v) * 24 + (jl & 15);
                                __nv_bfloat16 hi = __float2bfloat16_rn(val);
                                __nv_bfloat16 lo = __float2bfloat16_rn(val - __bfloat162float(hi));
                                if (qk) { Kh[idx] = hi; Kl[idx] = lo; }
                                else    { Qh[idx] = hi; Ql[idx] = lo; }
                            }
                        }
                    }
                }
            }
        }
        __syncthreads();

        // --- S_k += Q K^T on tensor cores (3 tiles/warp, both t's) ---
#pragma unroll
        for (int ti = 0; ti < 2; ++ti) {
#pragma unroll
            for (int j = 0; j < 3; ++j) {
                const unsigned blk = (unsigned)((ti * 3 + skq[j]) * 1536);
                const unsigned qa = blk + (unsigned)(smt[j] * 16 * 48) + sa_row;
                const unsigned kb = blk + (unsigned)(snt[j] * 8 * 48) + sb_row;
                unsigned ah[4], al[4], bh[2], bl[2];
                ldsm_x4(ah[0], ah[1], ah[2], ah[3], qhB + qa);
                ldsm_x4(al[0], al[1], al[2], al[3], qlB + qa);
                ldsm_x2(bh[0], bh[1], khB + kb);
                ldsm_x2(bl[0], bl[1], klB + kb);
                mma_bf16(S[j], ah, bh[0], bh[1]);
                mma_bf16(S[j], ah, bl[0], bl[1]);
                mma_bf16(S[j], al, bh[0], bh[1]);
            }
        }
    }

    // --- write chunk partials (guards discard pad rows/cols) ---
    {
        float* base = g_Spart + (chunk * 3 * 64 + n) * 625;
        const int srow = lane >> 2;
        const int scol = 2 * (lane & 3);
#pragma unroll
        for (int j = 0; j < 3; ++j) {
            float* bk_ = base + skq[j] * 64 * 625;
#pragma unroll
            for (int rr = 0; rr < 2; ++rr) {
                const int v = smt[j] * 16 + srow + rr * 8;
                if (v < 25) {
#pragma unroll
                    for (int jj = 0; jj < 2; ++jj) {
                        const int w = snt[j] * 8 + scol + jj;
                        if (w < 25) bk_[v * 25 + w] = S[j][rr * 2 + jj];
                    }
                }
            }
        }
    }
}

// ---------------------------------------------------------------------------
// Kernel 2: reduce chunk partials, softmax, add A.
// ---------------------------------------------------------------------------
__global__ __launch_bounds__(128) void softmax_kernel(const float* __restrict__ A)
{
    __shared__ float S[625];
    const int b = blockIdx.x;
    const int kq = b / 64, n = b % 64;
    const int tid = threadIdx.x;

    for (int e = tid; e < 625; e += 128) {
        float s = 0.f;
        int base = ((kq * 64) + n) * 625 + e;
#pragma unroll 6
        for (int ch = 0; ch < 30; ++ch) s += g_Spart[ch * 120000 + base];
        S[e] = s;
    }
    __syncthreads();

    if (tid < 25) {
        const int v = tid;
        float m = -1e30f;
#pragma unroll
        for (int w = 0; w < 25; ++w) {
            float z = S[v * 25 + w] * SCALE_D;
            m = fmaxf(m, z);
        }
        float p[25];
        float sum = 0.f;
#pragma unroll
        for (int w = 0; w < 25; ++w) {
            p[w] = expf(S[v * 25 + w] * SCALE_D - m);
            sum += p[w];
        }
        float inv = 1.f / sum;
        float* dst = g_Aad + ((kq * 64) + n) * 625 + v * 25;
        const float* Ab = A + kq * 625 + v * 25;
#pragma unroll
        for (int w = 0; w < 25; ++w) dst[w] = Ab[w] + p[w] * inv;
    }
}

// ---------------------------------------------------------------------------
// Kernel 3: main path, pipelined tensor-H (EXACT copy of the R11/R12 version).
// ---------------------------------------------------------------------------
#define SM_WHI   0
#define SM_WLO   25600
#define SM_XBUF  51200
#define SM_HS    69632
#define SM_AS    89232
#define SM_STG   97632
#define SM_CSUM  104800
#define SM_BSM   105120
#define SM_TOTAL 105888

__global__ __launch_bounds__(256) void main_kernel(
    const float* __restrict__ x, const float* __restrict__ W,
    const float* __restrict__ b, float* __restrict__ y)
{
    extern __shared__ char smraw[];
    __nv_bfloat16* Whi = (__nv_bfloat16*)(smraw + SM_WHI);
    __nv_bfloat16* Wlo = (__nv_bfloat16*)(smraw + SM_WLO);
    float* Hs   = (float*)(smraw + SM_HS);
    float* As   = (float*)(smraw + SM_AS);
    float* stg  = (float*)(smraw + SM_STG);
    float* csum = (float*)(smraw + SM_CSUM);
    float* bsm  = (float*)(smraw + SM_BSM);

    const int tid = threadIdx.x;
    const int lane = tid & 31;
    const int wid = tid >> 5;
    const int n = blockIdx.y;
    const int tc = blockIdx.x;

    for (int e = tid; e < 12288; e += 256) {
        float wv = W[e];
        __nv_bfloat16 hi = __float2bfloat16_rn(wv);
        __nv_bfloat16 lo = __float2bfloat16_rn(wv - __bfloat162float(hi));
        int c = e / 192, f = e % 192;
        Whi[c * 200 + f] = hi;
        Wlo[c * 200 + f] = lo;
    }
    for (int e = tid; e < 1008; e += 256) {
        int buf = e / 504, r = 25 + (e % 504) / 72, c = e % 72;
        __nv_bfloat16* Xh = (__nv_bfloat16*)(smraw + SM_XBUF + buf * 9216);
        __nv_bfloat16* Xl = Xh + 2304;
        Xh[r * 72 + c] = __float2bfloat16_rn(0.f);
        Xl[r * 72 + c] = __float2bfloat16_rn(0.f);
    }
    for (int e = tid; e < 1875; e += 256) {
        int k = e / 625, rem = e % 625;
        int v = rem / 25, w = rem % 25;
        As[k * 700 + v * 28 + w] = g_Aad[(k * 64 + n) * 625 + rem];
    }
    for (int e = tid; e < 225; e += 256) {
        int k = e / 75, r = e % 75;
        As[k * 700 + (r / 3) * 28 + 25 + (r % 3)] = 0.f;
    }
    if (tid < 192) bsm[tid] = b[tid];
    __syncthreads();

    if (tid < 75) {
        int k = tid / 25, w = tid % 25;
        float s = 0.f;
#pragma unroll
        for (int v = 0; v < 25; ++v) s += As[k * 700 + v * 28 + w];
        csum[tid] = s;
    }
    __syncthreads();

    const int vh    = (tid < 224) ? tid / 112 : 0;
    const int ytile = (tid < 224) ? tid % 112 : 0;
    const int w4 = ytile / 16;
    const int f4 = ytile % 16;
    u64 yb[4][2];
    if (tid < 224) {
#pragma unroll
        for (int j = 0; j < 4; ++j) {
            int w = w4 * 4 + j;
            if (vh == 0 && w < 25) {
#pragma unroll
                for (int p = 0; p < 2; ++p) {
                    int f0 = f4 * 4 + 2 * p;
                    float v0 = bsm[f0]     * csum[w] + bsm[64 + f0]     * csum[25 + w]
                             + bsm[128 + f0]     * csum[50 + w];
                    float v1 = bsm[f0 + 1] * csum[w] + bsm[64 + f0 + 1] * csum[25 + w]
                             + bsm[128 + f0 + 1] * csum[50 + w];
                    yb[j][p] = pk2(v0, v1);
                }
            } else { yb[j][0] = 0ull; yb[j][1] = 0ull; }
        }
    }

    {
        const float4* src = (const float4*)(x + (n * 300 + tc * 12) * 1600);
        __nv_bfloat16* Xh = (__nv_bfloat16*)(smraw + SM_XBUF);
        __nv_bfloat16* Xl = Xh + 2304;
        for (int e = tid; e < 400; e += 256) {
            float4 v = src[e];
            int r = e >> 4, c = (e & 15) * 4;
            __nv_bfloat16 h0 = __float2bfloat16_rn(v.x), h1 = __float2bfloat16_rn(v.y);
            __nv_bfloat16 h2 = __float2bfloat16_rn(v.z), h3 = __float2bfloat16_rn(v.w);
            Xh[r * 72 + c]     = h0; Xh[r * 72 + c + 1] = h1;
            Xh[r * 72 + c + 2] = h2; Xh[r * 72 + c + 3] = h3;
            Xl[r * 72 + c]     = __float2bfloat16_rn(v.x - __bfloat162float(h0));
            Xl[r * 72 + c + 1] = __float2bfloat16_rn(v.y - __bfloat162float(h1));
            Xl[r * 72 + c + 2] = __float2bfloat16_rn(v.z - __bfloat162float(h2));
            Xl[r * 72 + c + 3] = __float2bfloat16_rn(v.w - __bfloat162float(h3));
        }
    }
    __syncthreads();

    const int mt = wid >> 2;
    const int nb = wid & 3;
    const int arow = mt * 16 + ((lane >> 3) & 1) * 8 + (lane & 7);
    const unsigned aoff = (unsigned)(arow * 144 + (lane >> 4) * 16);
    const unsigned boff = (unsigned)((lane & 15) * 400 + (lane >> 4) * 16);
    const unsigned whiB = (unsigned)__cvta_generic_to_shared(Whi);
    const unsigned wloB = (unsigned)__cvta_generic_to_shared(Wlo);
    const unsigned xbufB = (unsigned)__cvta_generic_to_shared(smraw + SM_XBUF);

    for (int it = 0; it < 12; ++it) {
        const int t = tc * 12 + it;
        const unsigned xhiB = xbufB + (unsigned)((it & 1) * 9216);
        const unsigned xloB = xhiB + 4608;

        {
            float acc[6][4];
#pragma unroll
            for (int i = 0; i < 6; ++i)
#pragma unroll
                for (int j = 0; j < 4; ++j) acc[i][j] = 0.f;

#pragma unroll
            for (int ks = 0; ks < 4; ++ks) {
                unsigned ahi[4], alo[4];
                ldsm_x4(ahi[0], ahi[1], ahi[2], ahi[3], xhiB + aoff + ks * 32);
                ldsm_x4(alo[0], alo[1], alo[2], alo[3], xloB + aoff + ks * 32);
#pragma unroll
                for (int c3 = 0; c3 < 3; ++c3) {
                    const int chunk = nb + 4 * c3;
                    const unsigned kb = boff + (unsigned)(ks * 6400 + chunk * 32);
                    unsigned bh[4], bl[4];
                    ldsm_x4t(bh[0], bh[1], bh[2], bh[3], whiB + kb);
                    ldsm_x4t(bl[0], bl[1], bl[2], bl[3], wloB + kb);
                    float* a0 = acc[c3 * 2];
                    float* a1 = acc[c3 * 2 + 1];
                    mma_bf16(a0, ahi, bh[0], bh[1]);
                    mma_bf16(a0, ahi, bl[0], bl[1]);
                    mma_bf16(a0, alo, bh[0], bh[1]);
                    mma_bf16(a1, ahi, bh[2], bh[3]);
                    mma_bf16(a1, ahi, bl[2], bl[3]);
                    mma_bf16(a1, alo, bh[2], bh[3]);
                }
            }
            const int crow = mt * 16 + (lane >> 2);
            const int ccol = 2 * (lane & 3);
            const bool s0ok = (crow < 25);
            const bool s1ok = (crow + 8 < 25);
#pragma unroll
            for (int c3 = 0; c3 < 3; ++c3) {
#pragma unroll
                for (int nt = 0; nt < 2; ++nt) {
                    const int n0 = (nb + 4 * c3) * 16 + nt * 8;
                    const float* a = acc[c3 * 2 + nt];
                    if (s0ok) *(float2*)&Hs[crow * 196 + n0 + ccol]       = make_float2(a[0], a[1]);
                    if (s1ok) *(float2*)&Hs[(crow + 8) * 196 + n0 + ccol] = make_float2(a[2], a[3]);
                }
            }
        }
        __syncthreads();

        u64 s2[4][2];
        if (tid < 224) {
#pragma unroll
            for (int j = 0; j < 4; ++j) { s2[j][0] = yb[j][0]; s2[j][1] = yb[j][1]; }
            const int vbeg = vh ? 13 : 0;
            const int vend = vh ? 25 : 13;
            const ulonglong2* H2 = (const ulonglong2*)Hs;
#pragma unroll
            for (int k = 0; k < 3; ++k) {
                const float* Ab = As + k * 700 + w4 * 4;
                const int hidx = k * 16 + f4;
                for (int v = vbeg; v < vend; ++v) {
                    float4 a = *(const float4*)(Ab + v * 28);
                    ulonglong2 h = H2[v * 49 + hidx];
                    u64 d0 = pk2(a.x, a.x), d1 = pk2(a.y, a.y);
                    u64 d2 = pk2(a.z, a.z), d3 = pk2(a.w, a.w);
                    fma2(s2[0][0], d0, h.x); fma2(s2[0][1], d0, h.y);
                    fma2(s2[1][0], d1, h.x); fma2(s2[1][1], d1, h.y);
                    fma2(s2[2][0], d2, h.x); fma2(s2[2][1], d2, h.y);
                    fma2(s2[3][0], d3, h.x); fma2(s2[3][1], d3, h.y);
                }
            }
            if (vh == 1) {
                u64* st = (u64*)stg;
#pragma unroll
                for (int j = 0; j < 4; ++j) {
                    st[ytile * 8 + j * 2]     = s2[j][0];
                    st[ytile * 8 + j * 2 + 1] = s2[j][1];
                }
            }
        } else if (wid == 7 && it < 11) {
            const float4* src = (const float4*)(x + (n * 300 + t + 1) * 1600);
            __nv_bfloat16* Xh = (__nv_bfloat16*)(smraw + SM_XBUF + ((it + 1) & 1) * 9216);
            __nv_bfloat16* Xl = Xh + 2304;
            for (int e = lane; e < 400; e += 32) {
                float4 v = src[e];
                int r = e >> 4, c = (e & 15) * 4;
                __nv_bfloat16 h0 = __float2bfloat16_rn(v.x), h1 = __float2bfloat16_rn(v.y);
                __nv_bfloat16 h2 = __float2bfloat16_rn(v.z), h3 = __float2bfloat16_rn(v.w);
                Xh[r * 72 + c]     = h0; Xh[r * 72 + c + 1] = h1;
                Xh[r * 72 + c + 2] = h2; Xh[r * 72 + c + 3] = h3;
                Xl[r * 72 + c]     = __float2bfloat16_rn(v.x - __bfloat162float(h0));
                Xl[r * 72 + c + 1] = __float2bfloat16_rn(v.y - __bfloat162float(h1));
                Xl[r * 72 + c + 2] = __float2bfloat16_rn(v.z - __bfloat162float(h2));
                Xl[r * 72 + c + 3] = __float2bfloat16_rn(v.w - __bfloat162float(h3));
            }
        }
        __syncthreads();

        if (tid < 112) {
            const u64* st = (const u64*)stg;
            float4* yout = (float4*)(y + (n * 300 + t) * 1600);
#pragma unroll
            for (int j = 0; j < 4; ++j) {
                int w = w4 * 4 + j;
                if (w < 25) {
                    float p0, p1, p2, p3, o0, o1, o2, o3;
                    up2(s2[j][0], p0, p1);
                    up2(s2[j][1], p2, p3);
                    up2(st[ytile * 8 + j * 2],     o0, o1);
                    up2(st[ytile * 8 + j * 2 + 1], o2, o3);
                    yout[w * 16 + f4] = make_float4(p0 + o0, p1 + o1, p2 + o2, p3 + o3);
                }
            }
        }
    }
}

// ---------------------------------------------------------------------------
extern "C" void kernel_launch(void* const* d_in, const int* in_sizes, int n_in,
                              void* d_out, int out_size)
{
    const float* x  = (const float*)d_in[0];
    const float* A  = (const float*)d_in[1];
    const float* W  = (const float*)d_in[2];
    const float* b  = (const float*)d_in[3];
    const float* Wq = (const float*)d_in[4];
    const float* bq = (const float*)d_in[5];
    const float* Wk = (const float*)d_in[6];
    const float* bk = (const float*)d_in[7];
    float* y = (float*)d_out;

    cudaFuncSetAttribute(score_kernel, cudaFuncAttributeMaxDynamicSharedMemorySize, SC_TOTAL);
    cudaFuncSetAttribute(main_kernel,  cudaFuncAttributeMaxDynamicSharedMemorySize, SM_TOTAL);

    score_kernel<<<dim3(30, 64), 256, SC_TOTAL>>>(x, Wq, bq, Wk, bk);
    softmax_kernel<<<192, 128>>>(A);
    main_kernel<<<dim3(25, 64), 256, SM_TOTAL>>>(x, W, b, y);
}

// round 14
// speedup vs baseline: 1.3470x; 1.3470x over previous
#include <cuda_runtime.h>
#include <cuda_bf16.h>
#include <math.h>

// Shapes (fixed): N=64, T=300, V=25, C=64, K=3, F=64, I=16, d=T*I=4800
#define SCALE_D 0.014433756729740645f   // 1/sqrt(4800)

__device__ __forceinline__ void ldsm_x4(unsigned& r0, unsigned& r1, unsigned& r2, unsigned& r3, unsigned addr) {
    asm volatile("ldmatrix.sync.aligned.m8n8.x4.shared.b16 {%0,%1,%2,%3}, [%4];"
                 : "=r"(r0), "=r"(r1), "=r"(r2), "=r"(r3) : "r"(addr));
}
__device__ __forceinline__ void ldsm_x2(unsigned& r0, unsigned& r1, unsigned addr) {
    asm volatile("ldmatrix.sync.aligned.m8n8.x2.shared.b16 {%0,%1}, [%2];"
                 : "=r"(r0), "=r"(r1) : "r"(addr));
}
__device__ __forceinline__ void ldsm_x4t(unsigned& r0, unsigned& r1, unsigned& r2, unsigned& r3, unsigned addr) {
    asm volatile("ldmatrix.sync.aligned.m8n8.x4.trans.shared.b16 {%0,%1,%2,%3}, [%4];"
                 : "=r"(r0), "=r"(r1), "=r"(r2), "=r"(r3) : "r"(addr));
}
__device__ __forceinline__ void mma_bf16(float* c, const unsigned* a, unsigned b0, unsigned b1) {
    asm volatile("mma.sync.aligned.m16n8k16.row.col.f32.bf16.bf16.f32 "
                 "{%0,%1,%2,%3}, {%4,%5,%6,%7}, {%8,%9}, {%0,%1,%2,%3};"
                 : "+f"(c[0]), "+f"(c[1]), "+f"(c[2]), "+f"(c[3])
                 : "r"(a[0]), "r"(a[1]), "r"(a[2]), "r"(a[3]), "r"(b0), "r"(b1));
}
__device__ __forceinline__ unsigned pack_bf2(float a, float b) {
    __nv_bfloat162 h;
    h.x = __float2bfloat16_rn(a);
    h.y = __float2bfloat16_rn(b);
    return *(unsigned*)&h;
}

// Scratch (module-static device memory; no runtime allocation)
__device__ float g_Spart[30 * 3 * 64 * 625];   // [chunk][k][n][v*25+w] partial scores
__device__ float g_Aad[3 * 64 * 625];          // A_adapt [k][n][v*25+w]

// ---------------------------------------------------------------------------
// Kernel 1: attention scores, fully tensor-core + register-prefetched X.
// ---------------------------------------------------------------------------
#define SC_GHI   0            // bf16 [64][104]  13312 B
#define SC_GLO   13312
#define SC_XH    26624        // bf16 [64][72]    9216 B
#define SC_XL    35840
#define SC_QH    45056        // bf16 [2][3][32][24] 9216 B
#define SC_QL    54272
#define SC_KH    63488
#define SC_KL    72704
#define SC_BS    81920        // f32 [96]
#define SC_TOTAL 82304

__global__ __launch_bounds__(256, 2) void score_kernel(
    const float* __restrict__ x,
    const float* __restrict__ Wq, const float* __restrict__ bq,
    const float* __restrict__ Wk, const float* __restrict__ bk)
{
    extern __shared__ char smraw[];
    __nv_bfloat16* Ghi = (__nv_bfloat16*)(smraw + SC_GHI);
    __nv_bfloat16* Glo = (__nv_bfloat16*)(smraw + SC_GLO);
    __nv_bfloat16* Xh  = (__nv_bfloat16*)(smraw + SC_XH);
    __nv_bfloat16* Xl  = (__nv_bfloat16*)(smraw + SC_XL);
    __nv_bfloat16* Qh  = (__nv_bfloat16*)(smraw + SC_QH);
    __nv_bfloat16* Ql  = (__nv_bfloat16*)(smraw + SC_QL);
    __nv_bfloat16* Kh  = (__nv_bfloat16*)(smraw + SC_KH);
    __nv_bfloat16* Kl  = (__nv_bfloat16*)(smraw + SC_KL);
    float* bs = (float*)(smraw + SC_BS);

    const int tid = threadIdx.x;
    const int lane = tid & 31;
    const int wid = tid >> 5;
    const int chunk = blockIdx.x;
    const int n = blockIdx.y;

    for (int e = tid; e < 6144; e += 256) {
        int c = e / 96, j = e % 96;
        float v;
        if (j < 48)  v = Wq[(j >> 4) * 1024 + c * 16 + (j & 15)];
        else { int jj = j - 48; v = Wk[(jj >> 4) * 1024 + c * 16 + (jj & 15)]; }
        __nv_bfloat16 hi = __float2bfloat16_rn(v);
        Ghi[c * 104 + j] = hi;
        Glo[c * 104 + j] = __float2bfloat16_rn(v - __bfloat162float(hi));
    }
    if (tid < 96) bs[tid] = (tid < 48) ? bq[tid] : bk[tid - 48];
    for (int e = tid; e < 1008; e += 256) {
        int r = 50 + e / 72, c = e % 72;
        Xh[r * 72 + c] = __float2bfloat16_rn(0.f);
        Xl[r * 72 + c] = __float2bfloat16_rn(0.f);
    }

    const float* xn = x + (n * 300 + chunk * 10) * 1600;

    const int mt = wid >> 1;
    const int ncb = wid & 1;
    const int arow = mt * 16 + (lane & 15);
    const unsigned aoff = (unsigned)(arow * 144 + (lane >> 4) * 16);
    const unsigned boff = (unsigned)((lane & 15) * 208 + (lane >> 4) * 16);
    const unsigned xhB = (unsigned)__cvta_generic_to_shared(Xh);
    const unsigned xlB = (unsigned)__cvta_generic_to_shared(Xl);
    const unsigned ghB = (unsigned)__cvta_generic_to_shared(Ghi);
    const unsigned glB = (unsigned)__cvta_generic_to_shared(Glo);
    const int crow = mt * 16 + (lane >> 2);
    const int ccol = 2 * (lane & 3);

    const unsigned qhB = (unsigned)__cvta_generic_to_shared(Qh);
    const unsigned qlB = (unsigned)__cvta_generic_to_shared(Ql);
    const unsigned khB = (unsigned)__cvta_generic_to_shared(Kh);
    const unsigned klB = (unsigned)__cvta_generic_to_shared(Kl);
    int skq[3], smt[3], snt[3];
#pragma unroll
    for (int j = 0; j < 3; ++j) {
        int tau = wid * 3 + j;
        skq[j] = tau >> 3;
        smt[j] = (tau & 7) >> 2;
        snt[j] = tau & 3;
    }
    const unsigned sa_row = (unsigned)((lane & 15) * 48 + (lane >> 4) * 16);
    const unsigned sb_row = (unsigned)((lane & 7) * 48 + ((lane >> 3) & 1) * 16);

    float S[3][4];
#pragma unroll
    for (int j = 0; j < 3; ++j)
#pragma unroll
        for (int q = 0; q < 4; ++q) S[j][q] = 0.f;

    // prologue: prefetch X(step 0)
    float4 px0, px1, px2, px3;
    {
        const float4* src = (const float4*)xn;
        px0 = src[tid];
        px1 = src[tid + 256];
        px2 = src[tid + 512];
        if (tid < 32) px3 = src[tid + 768];
    }

    for (int step = 0; step < 5; ++step) {
        // STS X(step) from prefetched regs
        {
#pragma unroll
            for (int q = 0; q < 4; ++q) {
                int e = tid + q * 256;
                if (q == 3 && tid >= 32) break;
                float4 v = (q == 0) ? px0 : (q == 1) ? px1 : (q == 2) ? px2 : px3;
                int r = e >> 4, c = (e & 15) * 4;
                __nv_bfloat16 h0 = __float2bfloat16_rn(v.x), h1 = __float2bfloat16_rn(v.y);
                __nv_bfloat16 h2 = __float2bfloat16_rn(v.z), h3 = __float2bfloat16_rn(v.w);
                Xh[r * 72 + c]     = h0; Xh[r * 72 + c + 1] = h1;
                Xh[r * 72 + c + 2] = h2; Xh[r * 72 + c + 3] = h3;
                Xl[r * 72 + c]     = __float2bfloat16_rn(v.x - __bfloat162float(h0));
                Xl[r * 72 + c + 1] = __float2bfloat16_rn(v.y - __bfloat162float(h1));
                Xl[r * 72 + c + 2] = __float2bfloat16_rn(v.z - __bfloat162float(h2));
                Xl[r * 72 + c + 3] = __float2bfloat16_rn(v.w - __bfloat162float(h3));
            }
        }
        __syncthreads();

        // prefetch X(step+1) — latency hides behind E-mma
        if (step < 4) {
            const float4* src = (const float4*)(xn + (step + 1) * 3200);
            px0 = src[tid];
            px1 = src[tid + 256];
            px2 = src[tid + 512];
            if (tid < 32) px3 = src[tid + 768];
        }

        // E = X * G on tensor cores; fragments + bias -> bf16 Q/K hi/lo
        {
            float acc[6][4];
#pragma unroll
            for (int i = 0; i < 6; ++i)
#pragma unroll
                for (int j = 0; j < 4; ++j) acc[i][j] = 0.f;

#pragma unroll
            for (int ks = 0; ks < 4; ++ks) {
                unsigned ahi[4], alo[4];
                ldsm_x4(ahi[0], ahi[1], ahi[2], ahi[3], xhB + aoff + ks * 32);
                ldsm_x4(alo[0], alo[1], alo[2], alo[3], xlB + aoff + ks * 32);
#pragma unroll
                for (int c3 = 0; c3 < 3; ++c3) {
                    const int ch = ncb + 2 * c3;
                    const unsigned kb = boff + (unsigned)(ks * 3328 + ch * 32);
                    unsigned bh[4], bl[4];
                    ldsm_x4t(bh[0], bh[1], bh[2], bh[3], ghB + kb);
                    ldsm_x4t(bl[0], bl[1], bl[2], bl[3], glB + kb);
                    float* a0 = acc[c3 * 2];
                    float* a1 = acc[c3 * 2 + 1];
                    mma_bf16(a0, ahi, bh[0], bh[1]);
                    mma_bf16(a0, ahi, bl[0], bl[1]);
                    mma_bf16(a0, alo, bh[0], bh[1]);
                    mma_bf16(a1, ahi, bh[2], bh[3]);
                    mma_bf16(a1, ahi, bl[2], bl[3]);
                    mma_bf16(a1, alo, bh[2], bh[3]);
                }
            }
#pragma unroll
            for (int c3 = 0; c3 < 3; ++c3) {
                const int ch = ncb + 2 * c3;
#pragma unroll
                for (int nt = 0; nt < 2; ++nt) {
                    const float* a = acc[c3 * 2 + nt];
                    const int col0 = ch * 16 + nt * 8 + ccol;
#pragma unroll
                    for (int rr = 0; rr < 2; ++rr) {
                        const int r = crow + rr * 8;
                        if (r < 50) {
                            const int t2 = (r >= 25);
                            const int v = r - t2 * 25;
#pragma unroll
                            for (int jj = 0; jj < 2; ++jj) {
                                const int j = col0 + jj;
                                const float val = a[rr * 2 + jj] + bs[j];
                                const int qk = (j >= 48);
                                const int jl = j - qk * 48;
                                const int idx = ((t2 * 3 + (jl >> 4)) * 32 + v) * 24 + (jl & 15);
                                __nv_bfloat16 hi = __float2bfloat16_rn(val);
                                __nv_bfloat16 lo = __float2bfloat16_rn(val - __bfloat162float(hi));
                                if (qk) { Kh[idx] = hi; Kl[idx] = lo; }
                                else    { Qh[idx] = hi; Ql[idx] = lo; }
                            }
                        }
                    }
                }
            }
        }
        __syncthreads();

        // S_k += Q K^T on tensor cores (3 tiles/warp, both t's)
#pragma unroll
        for (int ti = 0; ti < 2; ++ti) {
#pragma unroll
            for (int j = 0; j < 3; ++j) {
                const unsigned blk = (unsigned)((ti * 3 + skq[j]) * 1536);
                const unsigned qa = blk + (unsigned)(smt[j] * 16 * 48) + sa_row;
                const unsigned kb = blk + (unsigned)(snt[j] * 8 * 48) + sb_row;
                unsigned ah[4], al[4], bh[2], bl[2];
                ldsm_x4(ah[0], ah[1], ah[2], ah[3], qhB + qa);
                ldsm_x4(al[0], al[1], al[2], al[3], qlB + qa);
                ldsm_x2(bh[0], bh[1], khB + kb);
                ldsm_x2(bl[0], bl[1], klB + kb);
                mma_bf16(S[j], ah, bh[0], bh[1]);
                mma_bf16(S[j], ah, bl[0], bl[1]);
                mma_bf16(S[j], al, bh[0], bh[1]);
            }
        }
    }

    {
        float* base = g_Spart + (chunk * 3 * 64 + n) * 625;
        const int srow = lane >> 2;
        const int scol = 2 * (lane & 3);
#pragma unroll
        for (int j = 0; j < 3; ++j) {
            float* bk_ = base + skq[j] * 64 * 625;
#pragma unroll
            for (int rr = 0; rr < 2; ++rr) {
                const int v = smt[j] * 16 + srow + rr * 8;
                if (v < 25) {
#pragma unroll
                    for (int jj = 0; jj < 2; ++jj) {
                        const int w = snt[j] * 8 + scol + jj;
                        if (w < 25) bk_[v * 25 + w] = S[j][rr * 2 + jj];
                    }
                }
            }
        }
    }
}

// ---------------------------------------------------------------------------
// Kernel 2: reduce chunk partials, softmax, add A.
// ---------------------------------------------------------------------------
__global__ __launch_bounds__(128) void softmax_kernel(const float* __restrict__ A)
{
    __shared__ float S[625];
    const int b = blockIdx.x;
    const int kq = b / 64, n = b % 64;
    const int tid = threadIdx.x;

    for (int e = tid; e < 625; e += 128) {
        float s = 0.f;
        int base = ((kq * 64) + n) * 625 + e;
#pragma unroll 6
        for (int ch = 0; ch < 30; ++ch) s += g_Spart[ch * 120000 + base];
        S[e] = s;
    }
    __syncthreads();

    if (tid < 25) {
        const int v = tid;
        float m = -1e30f;
#pragma unroll
        for (int w = 0; w < 25; ++w) {
            float z = S[v * 25 + w] * SCALE_D;
            m = fmaxf(m, z);
        }
        float p[25];
        float sum = 0.f;
#pragma unroll
        for (int w = 0; w < 25; ++w) {
            p[w] = expf(S[v * 25 + w] * SCALE_D - m);
            sum += p[w];
        }
        float inv = 1.f / sum;
        float* dst = g_Aad + ((kq * 64) + n) * 625 + v * 25;
        const float* Ab = A + kq * 625 + v * 25;
#pragma unroll
        for (int w = 0; w < 25; ++w) dst[w] = Ab[w] + p[w] * inv;
    }
}

// ---------------------------------------------------------------------------
// Kernel 3: main path, BOTH GEMMs on tensor cores.
// H = X*W (bf16 split) -> fragments convert in-register to bf16 Hbf.
// Y = At*H (bf16 split, At t-invariant), bias pre-loaded in accumulators.
// X(t+1) prefetched into registers during H-mma; single X buffer.
// ---------------------------------------------------------------------------
#define M_WHI 0        // bf16 [64][200]  25600 B
#define M_WLO 25600
#define M_XH  51200    // bf16 [32][72]    4608 B
#define M_XL  55808
#define M_HBH 60416    // bf16 [32][200]  12800 B
#define M_HBL 73216
#define M_ATH 86016    // bf16 [3][32][40]  7680 B
#define M_ATL 93696
#define M_CS  101376   // f32 [80]
#define M_BS  101696   // f32 [192]
#define M_TOT 102464

__global__ __launch_bounds__(256, 2) void main_kernel(
    const float* __restrict__ x, const float* __restrict__ W,
    const float* __restrict__ b, float* __restrict__ y)
{
    extern __shared__ char smraw[];
    __nv_bfloat16* Whi = (__nv_bfloat16*)(smraw + M_WHI);
    __nv_bfloat16* Wlo = (__nv_bfloat16*)(smraw + M_WLO);
    __nv_bfloat16* Xh  = (__nv_bfloat16*)(smraw + M_XH);
    __nv_bfloat16* Xl  = (__nv_bfloat16*)(smraw + M_XL);
    unsigned* Hbh32 = (unsigned*)(smraw + M_HBH);
    unsigned* Hbl32 = (unsigned*)(smraw + M_HBL);
    __nv_bfloat16* Ath = (__nv_bfloat16*)(smraw + M_ATH);
    __nv_bfloat16* Atl = (__nv_bfloat16*)(smraw + M_ATL);
    float* csum = (float*)(smraw + M_CS);
    float* bsm  = (float*)(smraw + M_BS);

    const int tid = threadIdx.x;
    const int lane = tid & 31;
    const int wid = tid >> 5;
    const int n = blockIdx.y;
    const int tc = blockIdx.x;

    // --- init ---
    for (int e = tid; e < 12288; e += 256) {
        float wv = W[e];
        __nv_bfloat16 hi = __float2bfloat16_rn(wv);
        __nv_bfloat16 lo = __float2bfloat16_rn(wv - __bfloat162float(hi));
        int c = e / 192, f = e % 192;
        Whi[c * 200 + f] = hi;
        Wlo[c * 200 + f] = lo;
    }
    for (int e = tid; e < 504; e += 256) {          // X pad rows 25-31
        int r = 25 + e / 72, c = e % 72;
        Xh[r * 72 + c] = __float2bfloat16_rn(0.f);
        Xl[r * 72 + c] = __float2bfloat16_rn(0.f);
    }
    for (int e = tid; e < 3840; e += 256) {          // zero whole At hi+lo
        ((unsigned*)(smraw + M_ATH))[e] = 0u;
    }
    if (tid < 192) bsm[tid] = b[tid];
    if (tid < 75) {
        int k = tid / 25, w = tid % 25;
        const float* Ag = g_Aad + (k * 64 + n) * 625;
        float s = 0.f;
#pragma unroll
        for (int v = 0; v < 25; ++v) s += Ag[v * 25 + w];
        csum[tid] = s;
    }
    __syncthreads();
    // scatter At = A^T (after zero fill; race-free post-barrier)
    for (int e = tid; e < 1875; e += 256) {
        int k = e / 625, rem = e % 625;
        int v = rem / 25, w = rem % 25;
        float a = g_Aad[(k * 64 + n) * 625 + rem];
        __nv_bfloat16 hi = __float2bfloat16_rn(a);
        int idx = k * 1280 + w * 40 + v;
        Ath[idx] = hi;
        Atl[idx] = __float2bfloat16_rn(a - __bfloat162float(hi));
    }
    // prologue: X(t0) -> Xbuf
    {
        const float4* src = (const float4*)(x + (n * 300 + tc * 12) * 1600);
        for (int e = tid; e < 400; e += 256) {
            float4 v = src[e];
            int r = e >> 4, c = (e & 15) * 4;
            __nv_bfloat16 h0 = __float2bfloat16_rn(v.x), h1 = __float2bfloat16_rn(v.y);
            __nv_bfloat16 h2 = __float2bfloat16_rn(v.z), h3 = __float2bfloat16_rn(v.w);
            Xh[r * 72 + c]     = h0; Xh[r * 72 + c + 1] = h1;
            Xh[r * 72 + c + 2] = h2; Xh[r * 72 + c + 3] = h3;
            Xl[r * 72 + c]     = __float2bfloat16_rn(v.x - __bfloat162float(h0));
            Xl[r * 72 + c + 1] = __float2bfloat16_rn(v.y - __bfloat162float(h1));
            Xl[r * 72 + c + 2] = __float2bfloat16_rn(v.z - __bfloat162float(h2));
            Xl[r * 72 + c + 3] = __float2bfloat16_rn(v.w - __bfloat162float(h3));
        }
    }
    __syncthreads();

    // --- H-mma decode (proven R11 pattern) ---
    const int mt = wid >> 2;
    const int nb = wid & 3;
    const int arow = mt * 16 + (lane & 15);
    const unsigned aoff = (unsigned)(arow * 144 + (lane >> 4) * 16);
    const unsigned boff = (unsigned)((lane & 15) * 400 + (lane >> 4) * 16);
    const unsigned whiB = (unsigned)__cvta_generic_to_shared(Whi);
    const unsigned wloB = (unsigned)__cvta_generic_to_shared(Wlo);
    const unsigned xhB = (unsigned)__cvta_generic_to_shared(Xh);
    const unsigned xlB = (unsigned)__cvta_generic_to_shared(Xl);
    const int crow = mt * 16 + (lane >> 2);
    const int ccol = 2 * (lane & 3);

    // --- Y-mma decode: warp = (mY, nq); tiles f-cols nq*16 + {0-7, 8-15} ---
    const int mY = wid >> 2;
    const int nq = wid & 3;
    const unsigned aoffY = (unsigned)((lane & 15) * 80 + (lane >> 4) * 16);
    const unsigned boffY = (unsigned)((lane & 15) * 400 + (lane >> 4) * 16);
    const unsigned athB = (unsigned)__cvta_generic_to_shared(Ath);
    const unsigned atlB = (unsigned)__cvta_generic_to_shared(Atl);
    const unsigned hbhB = (unsigned)__cvta_generic_to_shared(smraw + M_HBH);
    const unsigned hblB = (unsigned)__cvta_generic_to_shared(smraw + M_HBL);
    const int w0 = mY * 16 + (lane >> 2);
    const int w1 = w0 + 8;
    const int f0 = nq * 16 + ccol;      // tile tn adds tn*8

    // t-invariant bias for this thread's 8 output slots
    float ybr[2][4];
#pragma unroll
    for (int tn = 0; tn < 2; ++tn) {
        int f = f0 + tn * 8;
#pragma unroll
        for (int j = 0; j < 4; ++j) {
            int w = (j < 2) ? w0 : w1;
            int fc = f + (j & 1);
            float s = 0.f;
            if (w < 25)
#pragma unroll
                for (int k = 0; k < 3; ++k)
                    s += bsm[k * 64 + fc] * csum[k * 25 + w];
            ybr[tn][j] = s;
        }
    }

    for (int it = 0; it < 12; ++it) {
        const int t = tc * 12 + it;

        // prefetch X(t+1) into registers (latency hides behind H-mma)
        float4 px0, px1;
        {
            const int tp = (it < 11) ? t + 1 : t;
            const float4* src = (const float4*)(x + (n * 300 + tp) * 1600);
            px0 = src[tid];
            if (tid < 144) px1 = src[tid + 256];
        }

        // --- H = X*W tensor cores; fragments -> bf16 Hbf hi/lo ---
        {
            float acc[6][4];
#pragma unroll
            for (int i = 0; i < 6; ++i)
#pragma unroll
                for (int j = 0; j < 4; ++j) acc[i][j] = 0.f;

#pragma unroll
            for (int ks = 0; ks < 4; ++ks) {
                unsigned ahi[4], alo[4];
                ldsm_x4(ahi[0], ahi[1], ahi[2], ahi[3], xhB + aoff + ks * 32);
                ldsm_x4(alo[0], alo[1], alo[2], alo[3], xlB + aoff + ks * 32);
#pragma unroll
                for (int c3 = 0; c3 < 3; ++c3) {
                    const int chunk = nb + 4 * c3;
                    const unsigned kb = boff + (unsigned)(ks * 6400 + chunk * 32);
                    unsigned bh[4], bl[4];
                    ldsm_x4t(bh[0], bh[1], bh[2], bh[3], whiB + kb);
                    ldsm_x4t(bl[0], bl[1], bl[2], bl[3], wloB + kb);
                    float* a0 = acc[c3 * 2];
                    float* a1 = acc[c3 * 2 + 1];
                    mma_bf16(a0, ahi, bh[0], bh[1]);
                    mma_bf16(a0, ahi, bl[0], bl[1]);
                    mma_bf16(a0, alo, bh[0], bh[1]);
                    mma_bf16(a1, ahi, bh[2], bh[3]);
                    mma_bf16(a1, ahi, bl[2], bl[3]);
                    mma_bf16(a1, alo, bh[2], bh[3]);
                }
            }
#pragma unroll
            for (int c3 = 0; c3 < 3; ++c3) {
#pragma unroll
                for (int nt = 0; nt < 2; ++nt) {
                    const int n0 = (nb + 4 * c3) * 16 + nt * 8;
                    const float* a = acc[c3 * 2 + nt];
                    const int i0 = crow * 100 + (n0 + ccol) / 2;
                    const int i1 = (crow + 8) * 100 + (n0 + ccol) / 2;
                    Hbh32[i0] = pack_bf2(a[0], a[1]);
                    Hbl32[i0] = pack_bf2(a[0] - __bfloat162float(__float2bfloat16_rn(a[0])),
                                         a[1] - __bfloat162float(__float2bfloat16_rn(a[1])));
                    Hbh32[i1] = pack_bf2(a[2], a[3]);
                    Hbl32[i1] = pack_bf2(a[2] - __bfloat162float(__float2bfloat16_rn(a[2])),
                                         a[3] - __bfloat162float(__float2bfloat16_rn(a[3])));
                }
            }
        }
        __syncthreads();

        // --- STS X(t+1) (Xbuf free now) ---
        if (it < 11) {
#pragma unroll
            for (int q = 0; q < 2; ++q) {
                int e = tid + q * 256;
                if (q == 1 && tid >= 144) break;
                float4 v = (q == 0) ? px0 : px1;
                int r = e >> 4, c = (e & 15) * 4;
                __nv_bfloat16 h0 = __float2bfloat16_rn(v.x), h1 = __float2bfloat16_rn(v.y);
                __nv_bfloat16 h2 = __float2bfloat16_rn(v.z), h3 = __float2bfloat16_rn(v.w);
                Xh[r * 72 + c]     = h0; Xh[r * 72 + c + 1] = h1;
                Xh[r * 72 + c + 2] = h2; Xh[r * 72 + c + 3] = h3;
                Xl[r * 72 + c]     = __float2bfloat16_rn(v.x - __bfloat162float(h0));
                Xl[r * 72 + c + 1] = __float2bfloat16_rn(v.y - __bfloat162float(h1));
                Xl[r * 72 + c + 2] = __float2bfloat16_rn(v.z - __bfloat162float(h2));
                Xl[r * 72 + c + 3] = __float2bfloat16_rn(v.w - __bfloat162float(h3));
            }
        }

        // --- Y = At * H tensor cores (2 tiles/warp, bias-seeded) ---
        {
            float Yacc[2][4];
#pragma unroll
            for (int tn = 0; tn < 2; ++tn)
#pragma unroll
                for (int j = 0; j < 4; ++j) Yacc[tn][j] = ybr[tn][j];

#pragma unroll
            for (int k = 0; k < 3; ++k) {
#pragma unroll
                for (int ks = 0; ks < 2; ++ks) {
                    const unsigned qa = (unsigned)(k * 2560 + mY * 1280 + ks * 32) + aoffY;
                    const unsigned kb = (unsigned)(ks * 6400 + k * 128 + nq * 32) + boffY;
                    unsigned ah[4], al[4], bh[4], bl[4];
                    ldsm_x4(ah[0], ah[1], ah[2], ah[3], athB + qa);
                    ldsm_x4(al[0], al[1], al[2], al[3], atlB + qa);
                    ldsm_x4t(bh[0], bh[1], bh[2], bh[3], hbhB + kb);
                    ldsm_x4t(bl[0], bl[1], bl[2], bl[3], hblB + kb);
                    mma_bf16(Yacc[0], ah, bh[0], bh[1]);
                    mma_bf16(Yacc[0], ah, bl[0], bl[1]);
                    mma_bf16(Yacc[0], al, bh[0], bh[1]);
                    mma_bf16(Yacc[1], ah, bh[2], bh[3]);
                    mma_bf16(Yacc[1], ah, bl[2], bl[3]);
                    mma_bf16(Yacc[1], al, bh[2], bh[3]);
                }
            }
            float* yout = y + (n * 300 + t) * 1600;
#pragma unroll
            for (int tn = 0; tn < 2; ++tn) {
                int f = f0 + tn * 8;
                if (w0 < 25) *(float2*)&yout[w0 * 64 + f] = make_float2(Yacc[tn][0], Yacc[tn][1]);
                if (w1 < 25) *(float2*)&yout[w1 * 64 + f] = make_float2(Yacc[tn][2], Yacc[tn][3]);
            }
        }
        __syncthreads();
    }
}

// ---------------------------------------------------------------------------
extern "C" void kernel_launch(void* const* d_in, const int* in_sizes, int n_in,
                              void* d_out, int out_size)
{
    const float* x  = (const float*)d_in[0];
    const float* A  = (const float*)d_in[1];
    const float* W  = (const float*)d_in[2];
    const float* b  = (const float*)d_in[3];
    const float* Wq = (const float*)d_in[4];
    const float* bq = (const float*)d_in[5];
    const float* Wk = (const float*)d_in[6];
    const float* bk = (const float*)d_in[7];
    float* y = (float*)d_out;

    cudaFuncSetAttribute(score_kernel, cudaFuncAttributeMaxDynamicSharedMemorySize, SC_TOTAL);
    cudaFuncSetAttribute(main_kernel,  cudaFuncAttributeMaxDynamicSharedMemorySize, M_TOT);

    score_kernel<<<dim3(30, 64), 256, SC_TOTAL>>>(x, Wq, bq, Wk, bk);
    softmax_kernel<<<192, 128>>>(A);
    main_kernel<<<dim3(25, 64), 256, M_TOT>>>(x, W, b, y);
}

// round 15
// speedup vs baseline: 1.5264x; 1.1331x over previous
#include <cuda_runtime.h>
#include <cuda_bf16.h>
#include <math.h>

// Shapes (fixed): N=64, T=300, V=25, C=64, K=3, F=64, I=16, d=T*I=4800
#define SCALE_D 0.014433756729740645f   // 1/sqrt(4800)

__device__ __forceinline__ void ldsm_x4(unsigned& r0, unsigned& r1, unsigned& r2, unsigned& r3, unsigned addr) {
    asm volatile("ldmatrix.sync.aligned.m8n8.x4.shared.b16 {%0,%1,%2,%3}, [%4];"
                 : "=r"(r0), "=r"(r1), "=r"(r2), "=r"(r3) : "r"(addr));
}
__device__ __forceinline__ void ldsm_x2(unsigned& r0, unsigned& r1, unsigned addr) {
    asm volatile("ldmatrix.sync.aligned.m8n8.x2.shared.b16 {%0,%1}, [%2];"
                 : "=r"(r0), "=r"(r1) : "r"(addr));
}
__device__ __forceinline__ void ldsm_x4t(unsigned& r0, unsigned& r1, unsigned& r2, unsigned& r3, unsigned addr) {
    asm volatile("ldmatrix.sync.aligned.m8n8.x4.trans.shared.b16 {%0,%1,%2,%3}, [%4];"
                 : "=r"(r0), "=r"(r1), "=r"(r2), "=r"(r3) : "r"(addr));
}
__device__ __forceinline__ void mma_bf16(float* c, const unsigned* a, unsigned b0, unsigned b1) {
    asm volatile("mma.sync.aligned.m16n8k16.row.col.f32.bf16.bf16.f32 "
                 "{%0,%1,%2,%3}, {%4,%5,%6,%7}, {%8,%9}, {%0,%1,%2,%3};"
                 : "+f"(c[0]), "+f"(c[1]), "+f"(c[2]), "+f"(c[3])
                 : "r"(a[0]), "r"(a[1]), "r"(a[2]), "r"(a[3]), "r"(b0), "r"(b1));
}
// split two floats into packed bf16 hi pair + lo (residual) pair
__device__ __forceinline__ void split2(float a, float b, unsigned& hi, unsigned& lo) {
    __nv_bfloat162 h, l;
    h.x = __float2bfloat16_rn(a);
    h.y = __float2bfloat16_rn(b);
    l.x = __float2bfloat16_rn(a - __bfloat162float(h.x));
    l.y = __float2bfloat16_rn(b - __bfloat162float(h.y));
    hi = *(unsigned*)&h;
    lo = *(unsigned*)&l;
}

// Scratch (module-static device memory; no runtime allocation)
__device__ float g_Spart[30 * 3 * 64 * 625];   // [chunk][k][n][v*25+w] partial scores
__device__ float g_Aad[3 * 64 * 625];          // A_adapt [k][n][v*25+w]
// pre-converted bf16 hi/lo weights (prep_kernel fills these once per launch)
__device__ __align__(16) __nv_bfloat16 g_Whi_[12288], g_Wlo_[12288];  // [c=64][f=192]
__device__ __align__(16) __nv_bfloat16 g_Ghi_[6144],  g_Glo_[6144];   // [c=64][j=96]

// ---------------------------------------------------------------------------
// Kernel 0: weight conversion (once per launch, ~18K elements)
// ---------------------------------------------------------------------------
__global__ __launch_bounds__(256) void prep_kernel(
    const float* __restrict__ W,
    const float* __restrict__ Wq, const float* __restrict__ Wk)
{
    int e = blockIdx.x * 256 + threadIdx.x;
    if (e < 12288) {
        float wv = W[e];
        __nv_bfloat16 hi = __float2bfloat16_rn(wv);
        g_Whi_[e] = hi;
        g_Wlo_[e] = __float2bfloat16_rn(wv - __bfloat162float(hi));
    }
    if (e < 6144) {
        int c = e / 96, j = e % 96;
        float v;
        if (j < 48)  v = Wq[(j >> 4) * 1024 + c * 16 + (j & 15)];
        else { int jj = j - 48; v = Wk[(jj >> 4) * 1024 + c * 16 + (jj & 15)]; }
        __nv_bfloat16 hi = __float2bfloat16_rn(v);
        g_Ghi_[e] = hi;
        g_Glo_[e] = __float2bfloat16_rn(v - __bfloat162float(hi));
    }
}

// ---------------------------------------------------------------------------
// Kernel 1: attention scores, fully tensor-core, packed stores.
// ---------------------------------------------------------------------------
#define SC_GHI   0            // bf16 [64][104]  13312 B
#define SC_GLO   13312
#define SC_XH    26624        // bf16 [64][72]    9216 B
#define SC_XL    35840
#define SC_QH    45056        // bf16 [2][3][32][24] 9216 B
#define SC_QL    54272
#define SC_KH    63488
#define SC_KL    72704
#define SC_BS    81920        // f32 [96]
#define SC_TOTAL 82304

__global__ __launch_bounds__(256, 2) void score_kernel(
    const float* __restrict__ x,
    const float* __restrict__ bq, const float* __restrict__ bk)
{
    extern __shared__ char smraw[];
    __nv_bfloat16* Ghi = (__nv_bfloat16*)(smraw + SC_GHI);
    __nv_bfloat16* Glo = (__nv_bfloat16*)(smraw + SC_GLO);
    __nv_bfloat16* Xh  = (__nv_bfloat16*)(smraw + SC_XH);
    __nv_bfloat16* Xl  = (__nv_bfloat16*)(smraw + SC_XL);
    __nv_bfloat16* Qh  = (__nv_bfloat16*)(smraw + SC_QH);
    __nv_bfloat16* Ql  = (__nv_bfloat16*)(smraw + SC_QL);
    __nv_bfloat16* Kh  = (__nv_bfloat16*)(smraw + SC_KH);
    __nv_bfloat16* Kl  = (__nv_bfloat16*)(smraw + SC_KL);
    float* bs = (float*)(smraw + SC_BS);

    const int tid = threadIdx.x;
    const int lane = tid & 31;
    const int wid = tid >> 5;
    const int chunk = blockIdx.x;
    const int n = blockIdx.y;

    // G init: straight float4 copies of pre-converted bf16 (row remap 96->104)
    {
        const float4* gh = (const float4*)g_Ghi_;
        const float4* gl = (const float4*)g_Glo_;
        for (int e = tid; e < 768; e += 256) {
            int c = e / 12, jg = e % 12;
            *(float4*)&Ghi[c * 104 + jg * 8] = gh[e];
            *(float4*)&Glo[c * 104 + jg * 8] = gl[e];
        }
    }
    if (tid < 96) bs[tid] = (tid < 48) ? bq[tid] : bk[tid - 48];
    for (int e = tid; e < 252; e += 256) {     // zero X pad rows 50-63, uint2
        int r = 50 + e / 18, c = (e % 18) * 4;
        *(uint2*)&Xh[r * 72 + c] = make_uint2(0u, 0u);
        *(uint2*)&Xl[r * 72 + c] = make_uint2(0u, 0u);
    }

    const float* xn = x + (n * 300 + chunk * 10) * 1600;

    const int mt = wid >> 1;
    const int ncb = wid & 1;
    const int arow = mt * 16 + (lane & 15);
    const unsigned aoff = (unsigned)(arow * 144 + (lane >> 4) * 16);
    const unsigned boff = (unsigned)((lane & 15) * 208 + (lane >> 4) * 16);
    const unsigned xhB = (unsigned)__cvta_generic_to_shared(Xh);
    const unsigned xlB = (unsigned)__cvta_generic_to_shared(Xl);
    const unsigned ghB = (unsigned)__cvta_generic_to_shared(Ghi);
    const unsigned glB = (unsigned)__cvta_generic_to_shared(Glo);
    const int crow = mt * 16 + (lane >> 2);
    const int ccol = 2 * (lane & 3);

    const unsigned qhB = (unsigned)__cvta_generic_to_shared(Qh);
    const unsigned qlB = (unsigned)__cvta_generic_to_shared(Ql);
    const unsigned khB = (unsigned)__cvta_generic_to_shared(Kh);
    const unsigned klB = (unsigned)__cvta_generic_to_shared(Kl);
    int skq[3], smt[3], snt[3];
#pragma unroll
    for (int j = 0; j < 3; ++j) {
        int tau = wid * 3 + j;
        skq[j] = tau >> 3;
        smt[j] = (tau & 7) >> 2;
        snt[j] = tau & 3;
    }
    const unsigned sa_row = (unsigned)((lane & 15) * 48 + (lane >> 4) * 16);
    const unsigned sb_row = (unsigned)((lane & 7) * 48 + ((lane >> 3) & 1) * 16);

    float S[3][4];
#pragma unroll
    for (int j = 0; j < 3; ++j)
#pragma unroll
        for (int q = 0; q < 4; ++q) S[j][q] = 0.f;

    // prologue: prefetch X(step 0)
    float4 px0, px1, px2, px3;
    {
        const float4* src = (const float4*)xn;
        px0 = src[tid];
        px1 = src[tid + 256];
        px2 = src[tid + 512];
        if (tid < 32) px3 = src[tid + 768];
    }

    for (int step = 0; step < 5; ++step) {
        // STS X(step) from prefetched regs — packed STS.64
        {
#pragma unroll
            for (int q = 0; q < 4; ++q) {
                int e = tid + q * 256;
                if (q == 3 && tid >= 32) break;
                float4 v = (q == 0) ? px0 : (q == 1) ? px1 : (q == 2) ? px2 : px3;
                int r = e >> 4, c = (e & 15) * 4;
                unsigned h0, l0, h1, l1;
                split2(v.x, v.y, h0, l0);
                split2(v.z, v.w, h1, l1);
                *(uint2*)&Xh[r * 72 + c] = make_uint2(h0, h1);
                *(uint2*)&Xl[r * 72 + c] = make_uint2(l0, l1);
            }
        }
        __syncthreads();

        // prefetch X(step+1) — latency hides behind E-mma
        if (step < 4) {
            const float4* src = (const float4*)(xn + (step + 1) * 3200);
            px0 = src[tid];
            px1 = src[tid + 256];
            px2 = src[tid + 512];
            if (tid < 32) px3 = src[tid + 768];
        }

        // E = X * G on tensor cores; fragments + bias -> packed bf16 Q/K
        {
            float acc[6][4];
#pragma unroll
            for (int i = 0; i < 6; ++i)
#pragma unroll
                for (int j = 0; j < 4; ++j) acc[i][j] = 0.f;

#pragma unroll
            for (int ks = 0; ks < 4; ++ks) {
                unsigned ahi[4], alo[4];
                ldsm_x4(ahi[0], ahi[1], ahi[2], ahi[3], xhB + aoff + ks * 32);
                ldsm_x4(alo[0], alo[1], alo[2], alo[3], xlB + aoff + ks * 32);
#pragma unroll
                for (int c3 = 0; c3 < 3; ++c3) {
                    const int ch = ncb + 2 * c3;
                    const unsigned kb = boff + (unsigned)(ks * 3328 + ch * 32);
                    unsigned bh[4], bl[4];
                    ldsm_x4t(bh[0], bh[1], bh[2], bh[3], ghB + kb);
                    ldsm_x4t(bl[0], bl[1], bl[2], bl[3], glB + kb);
                    float* a0 = acc[c3 * 2];
                    float* a1 = acc[c3 * 2 + 1];
                    mma_bf16(a0, ahi, bh[0], bh[1]);
                    mma_bf16(a0, ahi, bl[0], bl[1]);
                    mma_bf16(a0, alo, bh[0], bh[1]);
                    mma_bf16(a1, ahi, bh[2], bh[3]);
                    mma_bf16(a1, ahi, bl[2], bl[3]);
                    mma_bf16(a1, alo, bh[2], bh[3]);
                }
            }
#pragma unroll
            for (int c3 = 0; c3 < 3; ++c3) {
                const int ch = ncb + 2 * c3;
#pragma unroll
                for (int nt = 0; nt < 2; ++nt) {
                    const float* a = acc[c3 * 2 + nt];
                    const int j = ch * 16 + nt * 8 + ccol;     // even; pair (j, j+1)
                    const int qk = (j >= 48);
                    const int jl = j - qk * 48;
#pragma unroll
                    for (int rr = 0; rr < 2; ++rr) {
                        const int r = crow + rr * 8;
                        if (r < 50) {
                            const int t2 = (r >= 25);
                            const int v = r - t2 * 25;
                            const int idx = ((t2 * 3 + (jl >> 4)) * 32 + v) * 24 + (jl & 15);
                            unsigned hi, lo;
                            split2(a[rr * 2] + bs[j], a[rr * 2 + 1] + bs[j + 1], hi, lo);
                            if (qk) { *(unsigned*)&Kh[idx] = hi; *(unsigned*)&Kl[idx] = lo; }
                            else    { *(unsigned*)&Qh[idx] = hi; *(unsigned*)&Ql[idx] = lo; }
                        }
                    }
                }
            }
        }
        __syncthreads();

        // S_k += Q K^T on tensor cores (3 tiles/warp, both t's)
#pragma unroll
        for (int ti = 0; ti < 2; ++ti) {
#pragma unroll
            for (int j = 0; j < 3; ++j) {
                const unsigned blk = (unsigned)((ti * 3 + skq[j]) * 1536);
                const unsigned qa = blk + (unsigned)(smt[j] * 16 * 48) + sa_row;
                const unsigned kb = blk + (unsigned)(snt[j] * 8 * 48) + sb_row;
                unsigned ah[4], al[4], bh[2], bl[2];
                ldsm_x4(ah[0], ah[1], ah[2], ah[3], qhB + qa);
                ldsm_x4(al[0], al[1], al[2], al[3], qlB + qa);
                ldsm_x2(bh[0], bh[1], khB + kb);
                ldsm_x2(bl[0], bl[1], klB + kb);
                mma_bf16(S[j], ah, bh[0], bh[1]);
                mma_bf16(S[j], ah, bl[0], bl[1]);
                mma_bf16(S[j], al, bh[0], bh[1]);
            }
        }
    }

    {
        float* base = g_Spart + (chunk * 3 * 64 + n) * 625;
        const int srow = lane >> 2;
        const int scol = 2 * (lane & 3);
#pragma unroll
        for (int j = 0; j < 3; ++j) {
            float* bk_ = base + skq[j] * 64 * 625;
#pragma unroll
            for (int rr = 0; rr < 2; ++rr) {
                const int v = smt[j] * 16 + srow + rr * 8;
                if (v < 25) {
#pragma unroll
                    for (int jj = 0; jj < 2; ++jj) {
                        const int w = snt[j] * 8 + scol + jj;
                        if (w < 25) bk_[v * 25 + w] = S[j][rr * 2 + jj];
                    }
                }
            }
        }
    }
}

// ---------------------------------------------------------------------------
// Kernel 2: reduce chunk partials, softmax, add A.
// ---------------------------------------------------------------------------
__global__ __launch_bounds__(128) void softmax_kernel(const float* __restrict__ A)
{
    __shared__ float S[625];
    const int b = blockIdx.x;
    const int kq = b / 64, n = b % 64;
    const int tid = threadIdx.x;

    for (int e = tid; e < 625; e += 128) {
        float s = 0.f;
        int base = ((kq * 64) + n) * 625 + e;
#pragma unroll 6
        for (int ch = 0; ch < 30; ++ch) s += g_Spart[ch * 120000 + base];
        S[e] = s;
    }
    __syncthreads();

    if (tid < 25) {
        const int v = tid;
        float m = -1e30f;
#pragma unroll
        for (int w = 0; w < 25; ++w) {
            float z = S[v * 25 + w] * SCALE_D;
            m = fmaxf(m, z);
        }
        float p[25];
        float sum = 0.f;
#pragma unroll
        for (int w = 0; w < 25; ++w) {
            p[w] = expf(S[v * 25 + w] * SCALE_D - m);
            sum += p[w];
        }
        float inv = 1.f / sum;
        float* dst = g_Aad + ((kq * 64) + n) * 625 + v * 25;
        const float* Ab = A + kq * 625 + v * 25;
#pragma unroll
        for (int w = 0; w < 25; ++w) dst[w] = Ab[w] + p[w] * inv;
    }
}

// ---------------------------------------------------------------------------
// Kernel 3: main path, both GEMMs tensor-core, packed stores, prefetched X.
// ---------------------------------------------------------------------------
#define M_WHI 0        // bf16 [64][200]  25600 B
#define M_WLO 25600
#define M_XH  51200    // bf16 [32][72]    4608 B
#define M_XL  55808
#define M_HBH 60416    // bf16 [32][200]  12800 B
#define M_HBL 73216
#define M_ATH 86016    // bf16 [3][32][40]  7680 B
#define M_ATL 93696
#define M_CS  101376   // f32 [80]
#define M_BS  101696   // f32 [192]
#define M_TOT 102464

__global__ __launch_bounds__(256, 2) void main_kernel(
    const float* __restrict__ x,
    const float* __restrict__ b, float* __restrict__ y)
{
    extern __shared__ char smraw[];
    __nv_bfloat16* Whi = (__nv_bfloat16*)(smraw + M_WHI);
    __nv_bfloat16* Wlo = (__nv_bfloat16*)(smraw + M_WLO);
    __nv_bfloat16* Xh  = (__nv_bfloat16*)(smraw + M_XH);
    __nv_bfloat16* Xl  = (__nv_bfloat16*)(smraw + M_XL);
    unsigned* Hbh32 = (unsigned*)(smraw + M_HBH);
    unsigned* Hbl32 = (unsigned*)(smraw + M_HBL);
    __nv_bfloat16* Ath = (__nv_bfloat16*)(smraw + M_ATH);
    __nv_bfloat16* Atl = (__nv_bfloat16*)(smraw + M_ATL);
    float* csum = (float*)(smraw + M_CS);
    float* bsm  = (float*)(smraw + M_BS);

    const int tid = threadIdx.x;
    const int lane = tid & 31;
    const int wid = tid >> 5;
    const int n = blockIdx.y;
    const int tc = blockIdx.x;

    // --- init: W from pre-converted globals (float4 copies, row 192->200) ---
    {
        const float4* wh = (const float4*)g_Whi_;
        const float4* wl = (const float4*)g_Wlo_;
        for (int e = tid; e < 1536; e += 256) {
            int c = e / 24, fg = e % 24;
            *(float4*)&Whi[c * 200 + fg * 8] = wh[e];
            *(float4*)&Wlo[c * 200 + fg * 8] = wl[e];
        }
    }
    for (int e = tid; e < 126; e += 256) {          // X pad rows 25-31, uint2
        int r = 25 + e / 18, c = (e % 18) * 4;
        *(uint2*)&Xh[r * 72 + c] = make_uint2(0u, 0u);
        *(uint2*)&Xl[r * 72 + c] = make_uint2(0u, 0u);
    }
    for (int e = tid; e < 3840; e += 256) {          // zero whole At hi+lo
        ((unsigned*)(smraw + M_ATH))[e] = 0u;
    }
    if (tid < 192) bsm[tid] = b[tid];
    if (tid < 75) {
        int k = tid / 25, w = tid % 25;
        const float* Ag = g_Aad + (k * 64 + n) * 625;
        float s = 0.f;
#pragma unroll
        for (int v = 0; v < 25; ++v) s += Ag[v * 25 + w];
        csum[tid] = s;
    }
    __syncthreads();
    // scatter At = A^T (after zero fill; race-free post-barrier)
    for (int e = tid; e < 1875; e += 256) {
        int k = e / 625, rem = e % 625;
        int v = rem / 25, w = rem % 25;
        float a = g_Aad[(k * 64 + n) * 625 + rem];
        __nv_bfloat16 hi = __float2bfloat16_rn(a);
        int idx = k * 1280 + w * 40 + v;
        Ath[idx] = hi;
        Atl[idx] = __float2bfloat16_rn(a - __bfloat162float(hi));
    }
    // prologue: X(t0) -> Xbuf (packed)
    {
        const float4* src = (const float4*)(x + (n * 300 + tc * 12) * 1600);
        for (int e = tid; e < 400; e += 256) {
            float4 v = src[e];
            int r = e >> 4, c = (e & 15) * 4;
            unsigned h0, l0, h1, l1;
            split2(v.x, v.y, h0, l0);
            split2(v.z, v.w, h1, l1);
            *(uint2*)&Xh[r * 72 + c] = make_uint2(h0, h1);
            *(uint2*)&Xl[r * 72 + c] = make_uint2(l0, l1);
        }
    }
    __syncthreads();

    // --- H-mma decode (proven pattern) ---
    const int mt = wid >> 2;
    const int nb = wid & 3;
    const int arow = mt * 16 + (lane & 15);
    const unsigned aoff = (unsigned)(arow * 144 + (lane >> 4) * 16);
    const unsigned boff = (unsigned)((lane & 15) * 400 + (lane >> 4) * 16);
    const unsigned whiB = (unsigned)__cvta_generic_to_shared(Whi);
    const unsigned wloB = (unsigned)__cvta_generic_to_shared(Wlo);
    const unsigned xhB = (unsigned)__cvta_generic_to_shared(Xh);
    const unsigned xlB = (unsigned)__cvta_generic_to_shared(Xl);
    const int crow = mt * 16 + (lane >> 2);
    const int ccol = 2 * (lane & 3);

    // --- Y-mma decode ---
    const int mY = wid >> 2;
    const int nq = wid & 3;
    const unsigned aoffY = (unsigned)((lane & 15) * 80 + (lane >> 4) * 16);
    const unsigned boffY = (unsigned)((lane & 15) * 400 + (lane >> 4) * 16);
    const unsigned athB = (unsigned)__cvta_generic_to_shared(Ath);
    const unsigned atlB = (unsigned)__cvta_generic_to_shared(Atl);
    const unsigned hbhB = (unsigned)__cvta_generic_to_shared(smraw + M_HBH);
    const unsigned hblB = (unsigned)__cvta_generic_to_shared(smraw + M_HBL);
    const int w0 = mY * 16 + (lane >> 2);
    const int w1 = w0 + 8;
    const int f0 = nq * 16 + ccol;

    float ybr[2][4];
#pragma unroll
    for (int tn = 0; tn < 2; ++tn) {
        int f = f0 + tn * 8;
#pragma unroll
        for (int j = 0; j < 4; ++j) {
            int w = (j < 2) ? w0 : w1;
            int fc = f + (j & 1);
            float s = 0.f;
            if (w < 25)
#pragma unroll
                for (int k = 0; k < 3; ++k)
                    s += bsm[k * 64 + fc] * csum[k * 25 + w];
            ybr[tn][j] = s;
        }
    }

    for (int it = 0; it < 12; ++it) {
        const int t = tc * 12 + it;

        // prefetch X(t+1) into registers (latency hides behind H-mma)
        float4 px0, px1;
        {
            const int tp = (it < 11) ? t + 1 : t;
            const float4* src = (const float4*)(x + (n * 300 + tp) * 1600);
            px0 = src[tid];
            if (tid < 144) px1 = src[tid + 256];
        }

        // --- H = X*W tensor cores; fragments -> packed bf16 Hbf hi/lo ---
        {
            float acc[6][4];
#pragma unroll
            for (int i = 0; i < 6; ++i)
#pragma unroll
                for (int j = 0; j < 4; ++j) acc[i][j] = 0.f;

#pragma unroll
            for (int ks = 0; ks < 4; ++ks) {
                unsigned ahi[4], alo[4];
                ldsm_x4(ahi[0], ahi[1], ahi[2], ahi[3], xhB + aoff + ks * 32);
                ldsm_x4(alo[0], alo[1], alo[2], alo[3], xlB + aoff + ks * 32);
#pragma unroll
                for (int c3 = 0; c3 < 3; ++c3) {
                    const int chunk = nb + 4 * c3;
                    const unsigned kb = boff + (unsigned)(ks * 6400 + chunk * 32);
                    unsigned bh[4], bl[4];
                    ldsm_x4t(bh[0], bh[1], bh[2], bh[3], whiB + kb);
                    ldsm_x4t(bl[0], bl[1], bl[2], bl[3], wloB + kb);
                    float* a0 = acc[c3 * 2];
                    float* a1 = acc[c3 * 2 + 1];
                    mma_bf16(a0, ahi, bh[0], bh[1]);
                    mma_bf16(a0, ahi, bl[0], bl[1]);
                    mma_bf16(a0, alo, bh[0], bh[1]);
                    mma_bf16(a1, ahi, bh[2], bh[3]);
                    mma_bf16(a1, ahi, bl[2], bl[3]);
                    mma_bf16(a1, alo, bh[2], bh[3]);
                }
            }
#pragma unroll
            for (int c3 = 0; c3 < 3; ++c3) {
#pragma unroll
                for (int nt = 0; nt < 2; ++nt) {
                    const int n0 = (nb + 4 * c3) * 16 + nt * 8;
                    const float* a = acc[c3 * 2 + nt];
                    const int i0 = crow * 100 + (n0 + ccol) / 2;
                    const int i1 = (crow + 8) * 100 + (n0 + ccol) / 2;
                    unsigned hi, lo;
                    split2(a[0], a[1], hi, lo);
                    Hbh32[i0] = hi; Hbl32[i0] = lo;
                    split2(a[2], a[3], hi, lo);
                    Hbh32[i1] = hi; Hbl32[i1] = lo;
                }
            }
        }
        __syncthreads();

        // --- STS X(t+1) (Xbuf free now), packed ---
        if (it < 11) {
#pragma unroll
            for (int q = 0; q < 2; ++q) {
                int e = tid + q * 256;
                if (q == 1 && tid >= 144) break;
                float4 v = (q == 0) ? px0 : px1;
                int r = e >> 4, c = (e & 15) * 4;
                unsigned h0, l0, h1, l1;
                split2(v.x, v.y, h0, l0);
                split2(v.z, v.w, h1, l1);
                *(uint2*)&Xh[r * 72 + c] = make_uint2(h0, h1);
                *(uint2*)&Xl[r * 72 + c] = make_uint2(l0, l1);
            }
        }

        // --- Y = At * H tensor cores (2 tiles/warp, bias-seeded) ---
        {
            float Yacc[2][4];
#pragma unroll
            for (int tn = 0; tn < 2; ++tn)
#pragma unroll
                for (int j = 0; j < 4; ++j) Yacc[tn][j] = ybr[tn][j];

#pragma unroll
            for (int k = 0; k < 3; ++k) {
#pragma unroll
                for (int ks = 0; ks < 2; ++ks) {
                    const unsigned qa = (unsigned)(k * 2560 + mY * 1280 + ks * 32) + aoffY;
                    const unsigned kb = (unsigned)(ks * 6400 + k * 128 + nq * 32) + boffY;
                    unsigned ah[4], al[4], bh[4], bl[4];
                    ldsm_x4(ah[0], ah[1], ah[2], ah[3], athB + qa);
                    ldsm_x4(al[0], al[1], al[2], al[3], atlB + qa);
                    ldsm_x4t(bh[0], bh[1], bh[2], bh[3], hbhB + kb);
                    ldsm_x4t(bl[0], bl[1], bl[2], bl[3], hblB + kb);
                    mma_bf16(Yacc[0], ah, bh[0], bh[1]);
                    mma_bf16(Yacc[0], ah, bl[0], bl[1]);
                    mma_bf16(Yacc[0], al, bh[0], bh[1]);
                    mma_bf16(Yacc[1], ah, bh[2], bh[3]);
                    mma_bf16(Yacc[1], ah, bl[2], bl[3]);
                    mma_bf16(Yacc[1], al, bh[2], bh[3]);
                }
            }
            float* yout = y + (n * 300 + t) * 1600;
#pragma unroll
            for (int tn = 0; tn < 2; ++tn) {
                int f = f0 + tn * 8;
                if (w0 < 25) *(float2*)&yout[w0 * 64 + f] = make_float2(Yacc[tn][0], Yacc[tn][1]);
                if (w1 < 25) *(float2*)&yout[w1 * 64 + f] = make_float2(Yacc[tn][2], Yacc[tn][3]);
            }
        }
        __syncthreads();
    }
}

// ---------------------------------------------------------------------------
extern "C" void kernel_launch(void* const* d_in, const int* in_sizes, int n_in,
                              void* d_out, int out_size)
{
    const float* x  = (const float*)d_in[0];
    const float* A  = (const float*)d_in[1];
    const float* W  = (const float*)d_in[2];
    const float* b  = (const float*)d_in[3];
    const float* Wq = (const float*)d_in[4];
    const float* bq = (const float*)d_in[5];
    const float* Wk = (const float*)d_in[6];
    const float* bk = (const float*)d_in[7];
    float* y = (float*)d_out;

    cudaFuncSetAttribute(score_kernel, cudaFuncAttributeMaxDynamicSharedMemorySize, SC_TOTAL);
    cudaFuncSetAttribute(main_kernel,  cudaFuncAttributeMaxDynamicSharedMemorySize, M_TOT);

    prep_kernel<<<48, 256>>>(W, Wq, Wk);
    score_kernel<<<dim3(30, 64), 256, SC_TOTAL>>>(x, bq, bk);
    softmax_kernel<<<192, 128>>>(A);
    main_kernel<<<dim3(25, 64), 256, M_TOT>>>(x, b, y);
}

// round 16
// speedup vs baseline: 2.0031x; 1.3124x over previous
#include <cuda_runtime.h>
#include <cuda_fp16.h>
#include <math.h>

// Shapes (fixed): N=64, T=300, V=25, C=64, K=3, F=64, I=16, d=T*I=4800
#define SCALE_D 0.014433756729740645f   // 1/sqrt(4800)

__device__ __forceinline__ void ldsm_x4(unsigned& r0, unsigned& r1, unsigned& r2, unsigned& r3, unsigned addr) {
    asm volatile("ldmatrix.sync.aligned.m8n8.x4.shared.b16 {%0,%1,%2,%3}, [%4];"
                 : "=r"(r0), "=r"(r1), "=r"(r2), "=r"(r3) : "r"(addr));
}
__device__ __forceinline__ void ldsm_x2(unsigned& r0, unsigned& r1, unsigned addr) {
    asm volatile("ldmatrix.sync.aligned.m8n8.x2.shared.b16 {%0,%1}, [%2];"
                 : "=r"(r0), "=r"(r1) : "r"(addr));
}
__device__ __forceinline__ void ldsm_x4t(unsigned& r0, unsigned& r1, unsigned& r2, unsigned& r3, unsigned addr) {
    asm volatile("ldmatrix.sync.aligned.m8n8.x4.trans.shared.b16 {%0,%1,%2,%3}, [%4];"
                 : "=r"(r0), "=r"(r1), "=r"(r2), "=r"(r3) : "r"(addr));
}
__device__ __forceinline__ void mma_f16(float* c, const unsigned* a, unsigned b0, unsigned b1) {
    asm volatile("mma.sync.aligned.m16n8k16.row.col.f32.f16.f16.f32 "
                 "{%0,%1,%2,%3}, {%4,%5,%6,%7}, {%8,%9}, {%0,%1,%2,%3};"
                 : "+f"(c[0]), "+f"(c[1]), "+f"(c[2]), "+f"(c[3])
                 : "r"(a[0]), "r"(a[1]), "r"(a[2]), "r"(a[3]), "r"(b0), "r"(b1));
}
// split two floats into packed fp16 hi pair + fp16 residual pair
__device__ __forceinline__ void split2h(float a, float b, unsigned& hi, unsigned& lo) {
    __half2 h, l;
    h.x = __float2half_rn(a);
    h.y = __float2half_rn(b);
    l.x = __float2half_rn(a - __half2float(h.x));
    l.y = __float2half_rn(b - __half2float(h.y));
    hi = *(unsigned*)&h;
    lo = *(unsigned*)&l;
}
__device__ __forceinline__ unsigned pack_h2(float a, float b) {
    __half2 h;
    h.x = __float2half_rn(a);
    h.y = __float2half_rn(b);
    return *(unsigned*)&h;
}

// Scratch (module-static device memory; no runtime allocation)
__device__ float g_Spart[30 * 3 * 64 * 625];   // [chunk][k][n][v*25+w] partial scores
__device__ float g_Aad[3 * 64 * 625];          // A_adapt [k][n][v*25+w]
// pre-converted fp16 weights (prep_kernel, once per launch)
__device__ __align__(16) __half g_Wh_[12288];  // [c=64][f=192]
__device__ __align__(16) __half g_Gh_[6144];   // [c=64][j=96]

// ---------------------------------------------------------------------------
// Kernel 0: weight conversion
// ---------------------------------------------------------------------------
__global__ __launch_bounds__(256) void prep_kernel(
    const float* __restrict__ W,
    const float* __restrict__ Wq, const float* __restrict__ Wk)
{
    int e = blockIdx.x * 256 + threadIdx.x;
    if (e < 12288) g_Wh_[e] = __float2half_rn(W[e]);
    if (e < 6144) {
        int c = e / 96, j = e % 96;
        float v;
        if (j < 48)  v = Wq[(j >> 4) * 1024 + c * 16 + (j & 15)];
        else { int jj = j - 48; v = Wk[(jj >> 4) * 1024 + c * 16 + (jj & 15)]; }
        g_Gh_[e] = __float2half_rn(v);
    }
}

// ---------------------------------------------------------------------------
// Kernel 1: attention scores, fully tensor-core, fp16 2-term.
// E = (Xh+Xl)*Gh ; S = (Qh+Ql)*Kh.
// ---------------------------------------------------------------------------
#define SC_GH    0            // f16 [64][104]  13312 B
#define SC_XH    13312        // f16 [64][72]    9216 B
#define SC_XL    22528
#define SC_QH    31744        // f16 [2][3][32][24] 9216 B
#define SC_QL    40960
#define SC_KH    50176
#define SC_BS    59392        // f32 [96]
#define SC_TOTAL 59776

__global__ __launch_bounds__(256, 2) void score_kernel(
    const float* __restrict__ x,
    const float* __restrict__ bq, const float* __restrict__ bk)
{
    extern __shared__ char smraw[];
    __half* Gh = (__half*)(smraw + SC_GH);
    __half* Xh = (__half*)(smraw + SC_XH);
    __half* Xl = (__half*)(smraw + SC_XL);
    __half* Qh = (__half*)(smraw + SC_QH);
    __half* Ql = (__half*)(smraw + SC_QL);
    __half* Kh = (__half*)(smraw + SC_KH);
    float* bs = (float*)(smraw + SC_BS);

    const int tid = threadIdx.x;
    const int lane = tid & 31;
    const int wid = tid >> 5;
    const int chunk = blockIdx.x;
    const int n = blockIdx.y;

    // G init: float4 copies (row remap 96->104)
    {
        const float4* gh = (const float4*)g_Gh_;
        for (int e = tid; e < 768; e += 256) {
            int c = e / 12, jg = e % 12;
            *(float4*)&Gh[c * 104 + jg * 8] = gh[e];
        }
    }
    if (tid < 96) bs[tid] = (tid < 48) ? bq[tid] : bk[tid - 48];
    for (int e = tid; e < 252; e += 256) {     // zero X pad rows 50-63
        int r = 50 + e / 18, c = (e % 18) * 4;
        *(uint2*)&Xh[r * 72 + c] = make_uint2(0u, 0u);
        *(uint2*)&Xl[r * 72 + c] = make_uint2(0u, 0u);
    }

    const float* xn = x + (n * 300 + chunk * 10) * 1600;

    const int mt = wid >> 1;
    const int ncb = wid & 1;
    const int arow = mt * 16 + (lane & 15);
    const unsigned aoff = (unsigned)(arow * 144 + (lane >> 4) * 16);
    const unsigned boff = (unsigned)((lane & 15) * 208 + (lane >> 4) * 16);
    const unsigned xhB = (unsigned)__cvta_generic_to_shared(Xh);
    const unsigned xlB = (unsigned)__cvta_generic_to_shared(Xl);
    const unsigned ghB = (unsigned)__cvta_generic_to_shared(Gh);
    const int crow = mt * 16 + (lane >> 2);
    const int ccol = 2 * (lane & 3);

    const unsigned qhB = (unsigned)__cvta_generic_to_shared(Qh);
    const unsigned qlB = (unsigned)__cvta_generic_to_shared(Ql);
    const unsigned khB = (unsigned)__cvta_generic_to_shared(Kh);
    int skq[3], smt[3], snt[3];
#pragma unroll
    for (int j = 0; j < 3; ++j) {
        int tau = wid * 3 + j;
        skq[j] = tau >> 3;
        smt[j] = (tau & 7) >> 2;
        snt[j] = tau & 3;
    }
    const unsigned sa_row = (unsigned)((lane & 15) * 48 + (lane >> 4) * 16);
    const unsigned sb_row = (unsigned)((lane & 7) * 48 + ((lane >> 3) & 1) * 16);

    float S[3][4];
#pragma unroll
    for (int j = 0; j < 3; ++j)
#pragma unroll
        for (int q = 0; q < 4; ++q) S[j][q] = 0.f;

    // prologue: prefetch X(step 0)
    float4 px0, px1, px2, px3;
    {
        const float4* src = (const float4*)xn;
        px0 = src[tid];
        px1 = src[tid + 256];
        px2 = src[tid + 512];
        if (tid < 32) px3 = src[tid + 768];
    }

    for (int step = 0; step < 5; ++step) {
        // STS X(step) from prefetched regs — packed STS.64
        {
#pragma unroll
            for (int q = 0; q < 4; ++q) {
                int e = tid + q * 256;
                if (q == 3 && tid >= 32) break;
                float4 v = (q == 0) ? px0 : (q == 1) ? px1 : (q == 2) ? px2 : px3;
                int r = e >> 4, c = (e & 15) * 4;
                unsigned h0, l0, h1, l1;
                split2h(v.x, v.y, h0, l0);
                split2h(v.z, v.w, h1, l1);
                *(uint2*)&Xh[r * 72 + c] = make_uint2(h0, h1);
                *(uint2*)&Xl[r * 72 + c] = make_uint2(l0, l1);
            }
        }
        __syncthreads();

        // prefetch X(step+1)
        if (step < 4) {
            const float4* src = (const float4*)(xn + (step + 1) * 3200);
            px0 = src[tid];
            px1 = src[tid + 256];
            px2 = src[tid + 512];
            if (tid < 32) px3 = src[tid + 768];
        }

        // E = (Xh+Xl) * Gh ; fragments + bias -> Q split / K single
        {
            float acc[6][4];
#pragma unroll
            for (int i = 0; i < 6; ++i)
#pragma unroll
                for (int j = 0; j < 4; ++j) acc[i][j] = 0.f;

#pragma unroll
            for (int ks = 0; ks < 4; ++ks) {
                unsigned ahi[4], alo[4];
                ldsm_x4(ahi[0], ahi[1], ahi[2], ahi[3], xhB + aoff + ks * 32);
                ldsm_x4(alo[0], alo[1], alo[2], alo[3], xlB + aoff + ks * 32);
#pragma unroll
                for (int c3 = 0; c3 < 3; ++c3) {
                    const int ch = ncb + 2 * c3;
                    const unsigned kb = boff + (unsigned)(ks * 3328 + ch * 32);
                    unsigned bh[4];
                    ldsm_x4t(bh[0], bh[1], bh[2], bh[3], ghB + kb);
                    float* a0 = acc[c3 * 2];
                    float* a1 = acc[c3 * 2 + 1];
                    mma_f16(a0, ahi, bh[0], bh[1]);
                    mma_f16(a0, alo, bh[0], bh[1]);
                    mma_f16(a1, ahi, bh[2], bh[3]);
                    mma_f16(a1, alo, bh[2], bh[3]);
                }
            }
#pragma unroll
            for (int c3 = 0; c3 < 3; ++c3) {
                const int ch = ncb + 2 * c3;
#pragma unroll
                for (int nt = 0; nt < 2; ++nt) {
                    const float* a = acc[c3 * 2 + nt];
                    const int j = ch * 16 + nt * 8 + ccol;     // even pair (j, j+1)
                    const int qk = (j >= 48);
                    const int jl = j - qk * 48;
#pragma unroll
                    for (int rr = 0; rr < 2; ++rr) {
                        const int r = crow + rr * 8;
                        if (r < 50) {
                            const int t2 = (r >= 25);
                            const int v = r - t2 * 25;
                            const int idx = ((t2 * 3 + (jl >> 4)) * 32 + v) * 24 + (jl & 15);
                            const float v0 = a[rr * 2] + bs[j];
                            const float v1 = a[rr * 2 + 1] + bs[j + 1];
                            if (qk) {
                                *(unsigned*)&Kh[idx] = pack_h2(v0, v1);
                            } else {
                                unsigned hi, lo;
                                split2h(v0, v1, hi, lo);
                                *(unsigned*)&Qh[idx] = hi;
                                *(unsigned*)&Ql[idx] = lo;
                            }
                        }
                    }
                }
            }
        }
        __syncthreads();

        // S_k += (Qh+Ql) Kh^T (3 tiles/warp, both t's)
#pragma unroll
        for (int ti = 0; ti < 2; ++ti) {
#pragma unroll
            for (int j = 0; j < 3; ++j) {
                const unsigned blk = (unsigned)((ti * 3 + skq[j]) * 1536);
                const unsigned qa = blk + (unsigned)(smt[j] * 16 * 48) + sa_row;
                const unsigned kb = blk + (unsigned)(snt[j] * 8 * 48) + sb_row;
                unsigned ah[4], al[4], bh[2];
                ldsm_x4(ah[0], ah[1], ah[2], ah[3], qhB + qa);
                ldsm_x4(al[0], al[1], al[2], al[3], qlB + qa);
                ldsm_x2(bh[0], bh[1], khB + kb);
                mma_f16(S[j], ah, bh[0], bh[1]);
                mma_f16(S[j], al, bh[0], bh[1]);
            }
        }
    }

    {
        float* base = g_Spart + (chunk * 3 * 64 + n) * 625;
        const int srow = lane >> 2;
        const int scol = 2 * (lane & 3);
#pragma unroll
        for (int j = 0; j < 3; ++j) {
            float* bk_ = base + skq[j] * 64 * 625;
#pragma unroll
            for (int rr = 0; rr < 2; ++rr) {
                const int v = smt[j] * 16 + srow + rr * 8;
                if (v < 25) {
#pragma unroll
                    for (int jj = 0; jj < 2; ++jj) {
                        const int w = snt[j] * 8 + scol + jj;
                        if (w < 25) bk_[v * 25 + w] = S[j][rr * 2 + jj];
                    }
                }
            }
        }
    }
}

// ---------------------------------------------------------------------------
// Kernel 2: reduce chunk partials, softmax, add A.
// ---------------------------------------------------------------------------
__global__ __launch_bounds__(128) void softmax_kernel(const float* __restrict__ A)
{
    __shared__ float S[625];
    const int b = blockIdx.x;
    const int kq = b / 64, n = b % 64;
    const int tid = threadIdx.x;

    for (int e = tid; e < 625; e += 128) {
        float s = 0.f;
        int base = ((kq * 64) + n) * 625 + e;
#pragma unroll 6
        for (int ch = 0; ch < 30; ++ch) s += g_Spart[ch * 120000 + base];
        S[e] = s;
    }
    __syncthreads();

    if (tid < 25) {
        const int v = tid;
        float m = -1e30f;
#pragma unroll
        for (int w = 0; w < 25; ++w) {
            float z = S[v * 25 + w] * SCALE_D;
            m = fmaxf(m, z);
        }
        float p[25];
        float sum = 0.f;
#pragma unroll
        for (int w = 0; w < 25; ++w) {
            p[w] = expf(S[v * 25 + w] * SCALE_D - m);
            sum += p[w];
        }
        float inv = 1.f / sum;
        float* dst = g_Aad + ((kq * 64) + n) * 625 + v * 25;
        const float* Ab = A + kq * 625 + v * 25;
#pragma unroll
        for (int w = 0; w < 25; ++w) dst[w] = Ab[w] + p[w] * inv;
    }
}

// ---------------------------------------------------------------------------
// Kernel 3: main path, fp16 2-term tensor GEMMs.
// H = (Xh+Xl)*Wh ; Y = (Ath+Atl)*Hh ; bias in accumulators; X prefetched.
// ---------------------------------------------------------------------------
#define M_WH  0        // f16 [64][200]  25600 B
#define M_XH  25600    // f16 [32][72]    4608 B
#define M_XL  30208
#define M_HB  34816    // f16 [32][200]  12800 B
#define M_ATH 47616    // f16 [3][32][40]  7680 B
#define M_ATL 55296
#define M_CS  62976    // f32 [80]
#define M_BS  63296    // f32 [192]
#define M_TOT 64064

__global__ __launch_bounds__(256, 2) void main_kernel(
    const float* __restrict__ x,
    const float* __restrict__ b, float* __restrict__ y)
{
    extern __shared__ char smraw[];
    __half* Wh = (__half*)(smraw + M_WH);
    __half* Xh = (__half*)(smraw + M_XH);
    __half* Xl = (__half*)(smraw + M_XL);
    unsigned* Hb32 = (unsigned*)(smraw + M_HB);
    __half* Ath = (__half*)(smraw + M_ATH);
    __half* Atl = (__half*)(smraw + M_ATL);
    float* csum = (float*)(smraw + M_CS);
    float* bsm  = (float*)(smraw + M_BS);

    const int tid = threadIdx.x;
    const int lane = tid & 31;
    const int wid = tid >> 5;
    const int n = blockIdx.y;
    const int tc = blockIdx.x;

    // --- init: W from pre-converted global (float4 copies, row 192->200) ---
    {
        const float4* wh = (const float4*)g_Wh_;
        for (int e = tid; e < 1536; e += 256) {
            int c = e / 24, fg = e % 24;
            *(float4*)&Wh[c * 200 + fg * 8] = wh[e];
        }
    }
    for (int e = tid; e < 126; e += 256) {          // X pad rows 25-31
        int r = 25 + e / 18, c = (e % 18) * 4;
        *(uint2*)&Xh[r * 72 + c] = make_uint2(0u, 0u);
        *(uint2*)&Xl[r * 72 + c] = make_uint2(0u, 0u);
    }
    for (int e = tid; e < 3840; e += 256) {          // zero At hi+lo (contiguous)
        ((unsigned*)(smraw + M_ATH))[e] = 0u;
    }
    if (tid < 192) bsm[tid] = b[tid];
    if (tid < 75) {
        int k = tid / 25, w = tid % 25;
        const float* Ag = g_Aad + (k * 64 + n) * 625;
        float s = 0.f;
#pragma unroll
        for (int v = 0; v < 25; ++v) s += Ag[v * 25 + w];
        csum[tid] = s;
    }
    __syncthreads();
    // scatter At = A^T (fp16 hi/lo)
    for (int e = tid; e < 1875; e += 256) {
        int k = e / 625, rem = e % 625;
        int v = rem / 25, w = rem % 25;
        float a = g_Aad[(k * 64 + n) * 625 + rem];
        __half hi = __float2half_rn(a);
        int idx = k * 1280 + w * 40 + v;
        Ath[idx] = hi;
        Atl[idx] = __float2half_rn(a - __half2float(hi));
    }
    // prologue: X(t0) -> Xbuf
    {
        const float4* src = (const float4*)(x + (n * 300 + tc * 12) * 1600);
        for (int e = tid; e < 400; e += 256) {
            float4 v = src[e];
            int r = e >> 4, c = (e & 15) * 4;
            unsigned h0, l0, h1, l1;
            split2h(v.x, v.y, h0, l0);
            split2h(v.z, v.w, h1, l1);
            *(uint2*)&Xh[r * 72 + c] = make_uint2(h0, h1);
            *(uint2*)&Xl[r * 72 + c] = make_uint2(l0, l1);
        }
    }
    __syncthreads();

    // --- H-mma decode ---
    const int mt = wid >> 2;
    const int nb = wid & 3;
    const int arow = mt * 16 + (lane & 15);
    const unsigned aoff = (unsigned)(arow * 144 + (lane >> 4) * 16);
    const unsigned boff = (unsigned)((lane & 15) * 400 + (lane >> 4) * 16);
    const unsigned whB = (unsigned)__cvta_generic_to_shared(Wh);
    const unsigned xhB = (unsigned)__cvta_generic_to_shared(Xh);
    const unsigned xlB = (unsigned)__cvta_generic_to_shared(Xl);
    const int crow = mt * 16 + (lane >> 2);
    const int ccol = 2 * (lane & 3);

    // --- Y-mma decode ---
    const int mY = wid >> 2;
    const int nq = wid & 3;
    const unsigned aoffY = (unsigned)((lane & 15) * 80 + (lane >> 4) * 16);
    const unsigned boffY = (unsigned)((lane & 15) * 400 + (lane >> 4) * 16);
    const unsigned athB = (unsigned)__cvta_generic_to_shared(Ath);
    const unsigned atlB = (unsigned)__cvta_generic_to_shared(Atl);
    const unsigned hbB  = (unsigned)__cvta_generic_to_shared(smraw + M_HB);
    const int w0 = mY * 16 + (lane >> 2);
    const int w1 = w0 + 8;
    const int f0 = nq * 16 + ccol;

    float ybr[2][4];
#pragma unroll
    for (int tn = 0; tn < 2; ++tn) {
        int f = f0 + tn * 8;
#pragma unroll
        for (int j = 0; j < 4; ++j) {
            int w = (j < 2) ? w0 : w1;
            int fc = f + (j & 1);
            float s = 0.f;
            if (w < 25)
#pragma unroll
                for (int k = 0; k < 3; ++k)
                    s += bsm[k * 64 + fc] * csum[k * 25 + w];
            ybr[tn][j] = s;
        }
    }

    for (int it = 0; it < 12; ++it) {
        const int t = tc * 12 + it;

        // prefetch X(t+1)
        float4 px0, px1;
        {
            const int tp = (it < 11) ? t + 1 : t;
            const float4* src = (const float4*)(x + (n * 300 + tp) * 1600);
            px0 = src[tid];
            if (tid < 144) px1 = src[tid + 256];
        }

        // --- H = (Xh+Xl)*Wh ; fragments -> packed fp16 Hb ---
        {
            float acc[6][4];
#pragma unroll
            for (int i = 0; i < 6; ++i)
#pragma unroll
                for (int j = 0; j < 4; ++j) acc[i][j] = 0.f;

#pragma unroll
            for (int ks = 0; ks < 4; ++ks) {
                unsigned ahi[4], alo[4];
                ldsm_x4(ahi[0], ahi[1], ahi[2], ahi[3], xhB + aoff + ks * 32);
                ldsm_x4(alo[0], alo[1], alo[2], alo[3], xlB + aoff + ks * 32);
#pragma unroll
                for (int c3 = 0; c3 < 3; ++c3) {
                    const int chunk = nb + 4 * c3;
                    const unsigned kb = boff + (unsigned)(ks * 6400 + chunk * 32);
                    unsigned bh[4];
                    ldsm_x4t(bh[0], bh[1], bh[2], bh[3], whB + kb);
                    float* a0 = acc[c3 * 2];
                    float* a1 = acc[c3 * 2 + 1];
                    mma_f16(a0, ahi, bh[0], bh[1]);
                    mma_f16(a0, alo, bh[0], bh[1]);
                    mma_f16(a1, ahi, bh[2], bh[3]);
                    mma_f16(a1, alo, bh[2], bh[3]);
                }
            }
#pragma unroll
            for (int c3 = 0; c3 < 3; ++c3) {
#pragma unroll
                for (int nt = 0; nt < 2; ++nt) {
                    const int n0 = (nb + 4 * c3) * 16 + nt * 8;
                    const float* a = acc[c3 * 2 + nt];
                    const int i0 = crow * 100 + (n0 + ccol) / 2;
                    const int i1 = (crow + 8) * 100 + (n0 + ccol) / 2;
                    Hb32[i0] = pack_h2(a[0], a[1]);
                    Hb32[i1] = pack_h2(a[2], a[3]);
                }
            }
        }
        __syncthreads();

        // --- STS X(t+1) ---
        if (it < 11) {
#pragma unroll
            for (int q = 0; q < 2; ++q) {
                int e = tid + q * 256;
                if (q == 1 && tid >= 144) break;
                float4 v = (q == 0) ? px0 : px1;
                int r = e >> 4, c = (e & 15) * 4;
                unsigned h0, l0, h1, l1;
                split2h(v.x, v.y, h0, l0);
                split2h(v.z, v.w, h1, l1);
                *(uint2*)&Xh[r * 72 + c] = make_uint2(h0, h1);
                *(uint2*)&Xl[r * 72 + c] = make_uint2(l0, l1);
            }
        }

        // --- Y = (Ath+Atl)*Hh (2 tiles/warp, bias-seeded) ---
        {
            float Yacc[2][4];
#pragma unroll
            for (int tn = 0; tn < 2; ++tn)
#pragma unroll
                for (int j = 0; j < 4; ++j) Yacc[tn][j] = ybr[tn][j];

#pragma unroll
            for (int k = 0; k < 3; ++k) {
#pragma unroll
                for (int ks = 0; ks < 2; ++ks) {
                    const unsigned qa = (unsigned)(k * 2560 + mY * 1280 + ks * 32) + aoffY;
                    const unsigned kb = (unsigned)(ks * 6400 + k * 128 + nq * 32) + boffY;
                    unsigned ah[4], al[4], bh[4];
                    ldsm_x4(ah[0], ah[1], ah[2], ah[3], athB + qa);
                    ldsm_x4(al[0], al[1], al[2], al[3], atlB + qa);
                    ldsm_x4t(bh[0], bh[1], bh[2], bh[3], hbB + kb);
                    mma_f16(Yacc[0], ah, bh[0], bh[1]);
                    mma_f16(Yacc[0], al, bh[0], bh[1]);
                    mma_f16(Yacc[1], ah, bh[2], bh[3]);
                    mma_f16(Yacc[1], al, bh[2], bh[3]);
                }
            }
            float* yout = y + (n * 300 + t) * 1600;
#pragma unroll
            for (int tn = 0; tn < 2; ++tn) {
                int f = f0 + tn * 8;
                if (w0 < 25) *(float2*)&yout[w0 * 64 + f] = make_float2(Yacc[tn][0], Yacc[tn][1]);
                if (w1 < 25) *(float2*)&yout[w1 * 64 + f] = make_float2(Yacc[tn][2], Yacc[tn][3]);
            }
        }
        __syncthreads();
    }
}

// ---------------------------------------------------------------------------
extern "C" void kernel_launch(void* const* d_in, const int* in_sizes, int n_in,
                              void* d_out, int out_size)
{
    const float* x  = (const float*)d_in[0];
    const float* A  = (const float*)d_in[1];
    const float* W  = (const float*)d_in[2];
    const float* b  = (const float*)d_in[3];
    const float* Wq = (const float*)d_in[4];
    const float* bq = (const float*)d_in[5];
    const float* Wk = (const float*)d_in[6];
    const float* bk = (const float*)d_in[7];
    float* y = (float*)d_out;

    cudaFuncSetAttribute(score_kernel, cudaFuncAttributeMaxDynamicSharedMemorySize, SC_TOTAL);
    cudaFuncSetAttribute(main_kernel,  cudaFuncAttributeMaxDynamicSharedMemorySize, M_TOT);

    prep_kernel<<<48, 256>>>(W, Wq, Wk);
    score_kernel<<<dim3(30, 64), 256, SC_TOTAL>>>(x, bq, bk);
    softmax_kernel<<<192, 128>>>(A);
    main_kernel<<<dim3(25, 64), 256, M_TOT>>>(x, b, y);
}

// round 17
// speedup vs baseline: 2.3604x; 1.1784x over previous
#include <cuda_runtime.h>
#include <cuda_fp16.h>
#include <math.h>

// Shapes (fixed): N=64, T=300, V=25, C=64, K=3, F=64, I=16, d=T*I=4800
#define SCALE_D 0.014433756729740645f   // 1/sqrt(4800)

__device__ __forceinline__ void ldsm_x4(unsigned& r0, unsigned& r1, unsigned& r2, unsigned& r3, unsigned addr) {
    asm volatile("ldmatrix.sync.aligned.m8n8.x4.shared.b16 {%0,%1,%2,%3}, [%4];"
                 : "=r"(r0), "=r"(r1), "=r"(r2), "=r"(r3) : "r"(addr));
}
__device__ __forceinline__ void ldsm_x2(unsigned& r0, unsigned& r1, unsigned addr) {
    asm volatile("ldmatrix.sync.aligned.m8n8.x2.shared.b16 {%0,%1}, [%2];"
                 : "=r"(r0), "=r"(r1) : "r"(addr));
}
__device__ __forceinline__ void ldsm_x4t(unsigned& r0, unsigned& r1, unsigned& r2, unsigned& r3, unsigned addr) {
    asm volatile("ldmatrix.sync.aligned.m8n8.x4.trans.shared.b16 {%0,%1,%2,%3}, [%4];"
                 : "=r"(r0), "=r"(r1), "=r"(r2), "=r"(r3) : "r"(addr));
}
__device__ __forceinline__ void mma_f16(float* c, const unsigned* a, unsigned b0, unsigned b1) {
    asm volatile("mma.sync.aligned.m16n8k16.row.col.f32.f16.f16.f32 "
                 "{%0,%1,%2,%3}, {%4,%5,%6,%7}, {%8,%9}, {%0,%1,%2,%3};"
                 : "+f"(c[0]), "+f"(c[1]), "+f"(c[2]), "+f"(c[3])
                 : "r"(a[0]), "r"(a[1]), "r"(a[2]), "r"(a[3]), "r"(b0), "r"(b1));
}
// split two floats into packed fp16 hi pair + fp16 residual pair
__device__ __forceinline__ void split2h(float a, float b, unsigned& hi, unsigned& lo) {
    __half2 h, l;
    h.x = __float2half_rn(a);
    h.y = __float2half_rn(b);
    l.x = __float2half_rn(a - __half2float(h.x));
    l.y = __float2half_rn(b - __half2float(h.y));
    hi = *(unsigned*)&h;
    lo = *(unsigned*)&l;
}
__device__ __forceinline__ unsigned pack_h2(float a, float b) {
    __half2 h;
    h.x = __float2half_rn(a);
    h.y = __float2half_rn(b);
    return *(unsigned*)&h;
}

// Scratch (module-static device memory; no runtime allocation)
__device__ float g_Spart[30 * 3 * 64 * 625];   // [chunk][k][n][v*25+w] partial scores
__device__ float g_Aad[3 * 64 * 625];          // A_adapt [k][n][v*25+w]
// pre-converted fp16 weights (prep_kernel, once per launch)
__device__ __align__(16) __half g_Wh_[12288];  // [c=64][f=192]
__device__ __align__(16) __half g_Gh_[6144];   // [c=64][j=96]

// ---------------------------------------------------------------------------
// Kernel 0: weight conversion
// ---------------------------------------------------------------------------
__global__ __launch_bounds__(256) void prep_kernel(
    const float* __restrict__ W,
    const float* __restrict__ Wq, const float* __restrict__ Wk)
{
    int e = blockIdx.x * 256 + threadIdx.x;
    if (e < 12288) g_Wh_[e] = __float2half_rn(W[e]);
    if (e < 6144) {
        int c = e / 96, j = e % 96;
        float v;
        if (j < 48)  v = Wq[(j >> 4) * 1024 + c * 16 + (j & 15)];
        else { int jj = j - 48; v = Wk[(jj >> 4) * 1024 + c * 16 + (jj & 15)]; }
        g_Gh_[e] = __float2half_rn(v);
    }
}

// ---------------------------------------------------------------------------
// Kernel 1: attention scores (EXACT copy of the R16 version, ~75 us).
// ---------------------------------------------------------------------------
#define SC_GH    0            // f16 [64][104]  13312 B
#define SC_XH    13312        // f16 [64][72]    9216 B
#define SC_XL    22528
#define SC_QH    31744        // f16 [2][3][32][24] 9216 B
#define SC_QL    40960
#define SC_KH    50176
#define SC_BS    59392        // f32 [96]
#define SC_TOTAL 59776

__global__ __launch_bounds__(256, 2) void score_kernel(
    const float* __restrict__ x,
    const float* __restrict__ bq, const float* __restrict__ bk)
{
    extern __shared__ char smraw[];
    __half* Gh = (__half*)(smraw + SC_GH);
    __half* Xh = (__half*)(smraw + SC_XH);
    __half* Xl = (__half*)(smraw + SC_XL);
    __half* Qh = (__half*)(smraw + SC_QH);
    __half* Ql = (__half*)(smraw + SC_QL);
    __half* Kh = (__half*)(smraw + SC_KH);
    float* bs = (float*)(smraw + SC_BS);

    const int tid = threadIdx.x;
    const int lane = tid & 31;
    const int wid = tid >> 5;
    const int chunk = blockIdx.x;
    const int n = blockIdx.y;

    {
        const float4* gh = (const float4*)g_Gh_;
        for (int e = tid; e < 768; e += 256) {
            int c = e / 12, jg = e % 12;
            *(float4*)&Gh[c * 104 + jg * 8] = gh[e];
        }
    }
    if (tid < 96) bs[tid] = (tid < 48) ? bq[tid] : bk[tid - 48];
    for (int e = tid; e < 252; e += 256) {
        int r = 50 + e / 18, c = (e % 18) * 4;
        *(uint2*)&Xh[r * 72 + c] = make_uint2(0u, 0u);
        *(uint2*)&Xl[r * 72 + c] = make_uint2(0u, 0u);
    }

    const float* xn = x + (n * 300 + chunk * 10) * 1600;

    const int mt = wid >> 1;
    const int ncb = wid & 1;
    const int arow = mt * 16 + (lane & 15);
    const unsigned aoff = (unsigned)(arow * 144 + (lane >> 4) * 16);
    const unsigned boff = (unsigned)((lane & 15) * 208 + (lane >> 4) * 16);
    const unsigned xhB = (unsigned)__cvta_generic_to_shared(Xh);
    const unsigned xlB = (unsigned)__cvta_generic_to_shared(Xl);
    const unsigned ghB = (unsigned)__cvta_generic_to_shared(Gh);
    const int crow = mt * 16 + (lane >> 2);
    const int ccol = 2 * (lane & 3);

    const unsigned qhB = (unsigned)__cvta_generic_to_shared(Qh);
    const unsigned qlB = (unsigned)__cvta_generic_to_shared(Ql);
    const unsigned khB = (unsigned)__cvta_generic_to_shared(Kh);
    int skq[3], smt[3], snt[3];
#pragma unroll
    for (int j = 0; j < 3; ++j) {
        int tau = wid * 3 + j;
        skq[j] = tau >> 3;
        smt[j] = (tau & 7) >> 2;
        snt[j] = tau & 3;
    }
    const unsigned sa_row = (unsigned)((lane & 15) * 48 + (lane >> 4) * 16);
    const unsigned sb_row = (unsigned)((lane & 7) * 48 + ((lane >> 3) & 1) * 16);

    float S[3][4];
#pragma unroll
    for (int j = 0; j < 3; ++j)
#pragma unroll
        for (int q = 0; q < 4; ++q) S[j][q] = 0.f;

    float4 px0, px1, px2, px3;
    {
        const float4* src = (const float4*)xn;
        px0 = src[tid];
        px1 = src[tid + 256];
        px2 = src[tid + 512];
        if (tid < 32) px3 = src[tid + 768];
    }

    for (int step = 0; step < 5; ++step) {
        {
#pragma unroll
            for (int q = 0; q < 4; ++q) {
                int e = tid + q * 256;
                if (q == 3 && tid >= 32) break;
                float4 v = (q == 0) ? px0 : (q == 1) ? px1 : (q == 2) ? px2 : px3;
                int r = e >> 4, c = (e & 15) * 4;
                unsigned h0, l0, h1, l1;
                split2h(v.x, v.y, h0, l0);
                split2h(v.z, v.w, h1, l1);
                *(uint2*)&Xh[r * 72 + c] = make_uint2(h0, h1);
                *(uint2*)&Xl[r * 72 + c] = make_uint2(l0, l1);
            }
        }
        __syncthreads();

        if (step < 4) {
            const float4* src = (const float4*)(xn + (step + 1) * 3200);
            px0 = src[tid];
            px1 = src[tid + 256];
            px2 = src[tid + 512];
            if (tid < 32) px3 = src[tid + 768];
        }

        {
            float acc[6][4];
#pragma unroll
            for (int i = 0; i < 6; ++i)
#pragma unroll
                for (int j = 0; j < 4; ++j) acc[i][j] = 0.f;

#pragma unroll
            for (int ks = 0; ks < 4; ++ks) {
                unsigned ahi[4], alo[4];
                ldsm_x4(ahi[0], ahi[1], ahi[2], ahi[3], xhB + aoff + ks * 32);
                ldsm_x4(alo[0], alo[1], alo[2], alo[3], xlB + aoff + ks * 32);
#pragma unroll
                for (int c3 = 0; c3 < 3; ++c3) {
                    const int ch = ncb + 2 * c3;
                    const unsigned kb = boff + (unsigned)(ks * 3328 + ch * 32);
                    unsigned bh[4];
                    ldsm_x4t(bh[0], bh[1], bh[2], bh[3], ghB + kb);
                    float* a0 = acc[c3 * 2];
                    float* a1 = acc[c3 * 2 + 1];
                    mma_f16(a0, ahi, bh[0], bh[1]);
                    mma_f16(a0, alo, bh[0], bh[1]);
                    mma_f16(a1, ahi, bh[2], bh[3]);
                    mma_f16(a1, alo, bh[2], bh[3]);
                }
            }
#pragma unroll
            for (int c3 = 0; c3 < 3; ++c3) {
                const int ch = ncb + 2 * c3;
#pragma unroll
                for (int nt = 0; nt < 2; ++nt) {
                    const float* a = acc[c3 * 2 + nt];
                    const int j = ch * 16 + nt * 8 + ccol;
                    const int qk = (j >= 48);
                    const int jl = j - qk * 48;
#pragma unroll
                    for (int rr = 0; rr < 2; ++rr) {
                        const int r = crow + rr * 8;
                        if (r < 50) {
                            const int t2 = (r >= 25);
                            const int v = r - t2 * 25;
                            const int idx = ((t2 * 3 + (jl >> 4)) * 32 + v) * 24 + (jl & 15);
                            const float v0 = a[rr * 2] + bs[j];
                            const float v1 = a[rr * 2 + 1] + bs[j + 1];
                            if (qk) {
                                *(unsigned*)&Kh[idx] = pack_h2(v0, v1);
                            } else {
                                unsigned hi, lo;
                                split2h(v0, v1, hi, lo);
                                *(unsigned*)&Qh[idx] = hi;
                                *(unsigned*)&Ql[idx] = lo;
                            }
                        }
                    }
                }
            }
        }
        __syncthreads();

#pragma unroll
        for (int ti = 0; ti < 2; ++ti) {
#pragma unroll
            for (int j = 0; j < 3; ++j) {
                const unsigned blk = (unsigned)((ti * 3 + skq[j]) * 1536);
                const unsigned qa = blk + (unsigned)(smt[j] * 16 * 48) + sa_row;
                const unsigned kb = blk + (unsigned)(snt[j] * 8 * 48) + sb_row;
                unsigned ah[4], al[4], bh[2];
                ldsm_x4(ah[0], ah[1], ah[2], ah[3], qhB + qa);
                ldsm_x4(al[0], al[1], al[2], al[3], qlB + qa);
                ldsm_x2(bh[0], bh[1], khB + kb);
                mma_f16(S[j], ah, bh[0], bh[1]);
                mma_f16(S[j], al, bh[0], bh[1]);
            }
        }
    }

    {
        float* base = g_Spart + (chunk * 3 * 64 + n) * 625;
        const int srow = lane >> 2;
        const int scol = 2 * (lane & 3);
#pragma unroll
        for (int j = 0; j < 3; ++j) {
            float* bk_ = base + skq[j] * 64 * 625;
#pragma unroll
            for (int rr = 0; rr < 2; ++rr) {
                const int v = smt[j] * 16 + srow + rr * 8;
                if (v < 25) {
#pragma unroll
                    for (int jj = 0; jj < 2; ++jj) {
                        const int w = snt[j] * 8 + scol + jj;
                        if (w < 25) bk_[v * 25 + w] = S[j][rr * 2 + jj];
                    }
                }
            }
        }
    }
}

// ---------------------------------------------------------------------------
// Kernel 2: reduce chunk partials, softmax, add A.
// ---------------------------------------------------------------------------
__global__ __launch_bounds__(128) void softmax_kernel(const float* __restrict__ A)
{
    __shared__ float S[625];
    const int b = blockIdx.x;
    const int kq = b / 64, n = b % 64;
    const int tid = threadIdx.x;

    for (int e = tid; e < 625; e += 128) {
        float s = 0.f;
        int base = ((kq * 64) + n) * 625 + e;
#pragma unroll 6
        for (int ch = 0; ch < 30; ++ch) s += g_Spart[ch * 120000 + base];
        S[e] = s;
    }
    __syncthreads();

    if (tid < 25) {
        const int v = tid;
        float m = -1e30f;
#pragma unroll
        for (int w = 0; w < 25; ++w) {
            float z = S[v * 25 + w] * SCALE_D;
            m = fmaxf(m, z);
        }
        float p[25];
        float sum = 0.f;
#pragma unroll
        for (int w = 0; w < 25; ++w) {
            p[w] = expf(S[v * 25 + w] * SCALE_D - m);
            sum += p[w];
        }
        float inv = 1.f / sum;
        float* dst = g_Aad + ((kq * 64) + n) * 625 + v * 25;
        const float* Ab = A + kq * 625 + v * 25;
#pragma unroll
        for (int w = 0; w < 25; ++w) dst[w] = Ab[w] + p[w] * inv;
    }
}

// ---------------------------------------------------------------------------
// Kernel 3: main path, fp16 2-term, 2 t's batched per iteration.
// X/H stacked: t0 rows 0-24, t1 rows 32-56 (pads zeroed). W fragments reused
// across 2 m-tiles; At fragments reused across 2 t's. 2 barriers per 2t.
// ---------------------------------------------------------------------------
#define M_WH  0        // f16 [64][200]  25600 B
#define M_XH  25600    // f16 [64][72]    9216 B
#define M_XL  34816
#define M_HB  44032    // f16 [64][200]  25600 B
#define M_ATH 69632    // f16 [3][32][40]  7680 B
#define M_ATL 77312
#define M_CS  84992    // f32 [80]
#define M_BS  85312    // f32 [192]
#define M_TOT 86080

__global__ __launch_bounds__(256, 2) void main_kernel(
    const float* __restrict__ x,
    const float* __restrict__ b, float* __restrict__ y)
{
    extern __shared__ char smraw[];
    __half* Wh = (__half*)(smraw + M_WH);
    __half* Xh = (__half*)(smraw + M_XH);
    __half* Xl = (__half*)(smraw + M_XL);
    unsigned* Hb32 = (unsigned*)(smraw + M_HB);
    __half* Ath = (__half*)(smraw + M_ATH);
    __half* Atl = (__half*)(smraw + M_ATL);
    float* csum = (float*)(smraw + M_CS);
    float* bsm  = (float*)(smraw + M_BS);

    const int tid = threadIdx.x;
    const int lane = tid & 31;
    const int wid = tid >> 5;
    const int n = blockIdx.y;
    const int tc = blockIdx.x;

    // --- init ---
    {
        const float4* wh = (const float4*)g_Wh_;
        for (int e = tid; e < 1536; e += 256) {
            int c = e / 24, fg = e % 24;
            *(float4*)&Wh[c * 200 + fg * 8] = wh[e];
        }
    }
    for (int e = tid; e < 252; e += 256) {     // zero X pad rows 25-31 & 57-63
        int rr = e / 18;
        int r = 25 + rr + ((rr >= 7) ? 25 : 0);
        int c = (e % 18) * 4;
        *(uint2*)&Xh[r * 72 + c] = make_uint2(0u, 0u);
        *(uint2*)&Xl[r * 72 + c] = make_uint2(0u, 0u);
    }
    for (int e = tid; e < 3840; e += 256) {    // zero At hi+lo
        ((unsigned*)(smraw + M_ATH))[e] = 0u;
    }
    if (tid < 192) bsm[tid] = b[tid];
    if (tid < 75) {
        int k = tid / 25, w = tid % 25;
        const float* Ag = g_Aad + (k * 64 + n) * 625;
        float s = 0.f;
#pragma unroll
        for (int v = 0; v < 25; ++v) s += Ag[v * 25 + w];
        csum[tid] = s;
    }
    __syncthreads();
    for (int e = tid; e < 1875; e += 256) {    // scatter At = A^T
        int k = e / 625, rem = e % 625;
        int v = rem / 25, w = rem % 25;
        float a = g_Aad[(k * 64 + n) * 625 + rem];
        __half hi = __float2half_rn(a);
        int idx = k * 1280 + w * 40 + v;
        Ath[idx] = hi;
        Atl[idx] = __float2half_rn(a - __half2float(hi));
    }
    // prologue: X(t0,t1) -> Xbuf (t0 rows 0-24, t1 rows 32-56)
    {
        const float4* src = (const float4*)(x + (n * 300 + tc * 12) * 1600);
        for (int e = tid; e < 800; e += 256) {
            float4 v = src[e];
            int tile = e / 400, er = e % 400;
            int r = (er >> 4) + tile * 32, c = (er & 15) * 4;
            unsigned h0, l0, h1, l1;
            split2h(v.x, v.y, h0, l0);
            split2h(v.z, v.w, h1, l1);
            *(uint2*)&Xh[r * 72 + c] = make_uint2(h0, h1);
            *(uint2*)&Xl[r * 72 + c] = make_uint2(l0, l1);
        }
    }
    __syncthreads();

    // --- H-mma decode: mp = t-half, warp covers 2 m-tiles x 3 chunks ---
    const int mp = wid >> 2;       // 0 -> t0 (rows 0-31), 1 -> t1 (rows 32-63)
    const int nb = wid & 3;        // chunks nb + 4*c3 (12 chunks of 16 cols)
    const unsigned aoff0 = (unsigned)((32 * mp + (lane & 15)) * 144 + (lane >> 4) * 16);
    const unsigned boff = (unsigned)((lane & 15) * 400 + (lane >> 4) * 16);
    const unsigned whB = (unsigned)__cvta_generic_to_shared(Wh);
    const unsigned xhB = (unsigned)__cvta_generic_to_shared(Xh);
    const unsigned xlB = (unsigned)__cvta_generic_to_shared(Xl);
    const int crow0 = 32 * mp + (lane >> 2);
    const int ccol = 2 * (lane & 3);

    // --- Y-mma decode ---
    const int mY = wid >> 2;       // w-tile (0: w0-15, 1: w16-24+pad)
    const int nq = wid & 3;        // f-chunk of 16 within 64
    const unsigned aoffY = (unsigned)((lane & 15) * 80 + (lane >> 4) * 16);
    const unsigned boffY = (unsigned)((lane & 15) * 400 + (lane >> 4) * 16);
    const unsigned athB = (unsigned)__cvta_generic_to_shared(Ath);
    const unsigned atlB = (unsigned)__cvta_generic_to_shared(Atl);
    const unsigned hbB  = (unsigned)__cvta_generic_to_shared(smraw + M_HB);
    const int w0 = mY * 16 + (lane >> 2);
    const int w1 = w0 + 8;
    const int f0 = nq * 16 + ccol;

    float ybr[2][4];
#pragma unroll
    for (int tn = 0; tn < 2; ++tn) {
        int f = f0 + tn * 8;
#pragma unroll
        for (int j = 0; j < 4; ++j) {
            int w = (j < 2) ? w0 : w1;
            int fc = f + (j & 1);
            float s = 0.f;
            if (w < 25)
#pragma unroll
                for (int k = 0; k < 3; ++k)
                    s += bsm[k * 64 + fc] * csum[k * 25 + w];
            ybr[tn][j] = s;
        }
    }

    for (int it2 = 0; it2 < 6; ++it2) {
        const int t0 = tc * 12 + it2 * 2;

        // prefetch X(next 2t) into registers
        float4 px0, px1, px2, px3;
        if (it2 < 5) {
            const float4* src = (const float4*)(x + (n * 300 + t0 + 2) * 1600);
            px0 = src[tid];
            px1 = src[tid + 256];
            px2 = src[tid + 512];
            if (tid < 32) px3 = src[tid + 768];
        }

        // --- H = (Xh+Xl)*Wh for both t's; W fragments shared by 2 m-tiles ---
        {
            float acc[2][6][4];
#pragma unroll
            for (int m = 0; m < 2; ++m)
#pragma unroll
                for (int i = 0; i < 6; ++i)
#pragma unroll
                    for (int j = 0; j < 4; ++j) acc[m][i][j] = 0.f;

#pragma unroll
            for (int ks = 0; ks < 4; ++ks) {
                unsigned a0h[4], a0l[4], a1h[4], a1l[4];
                ldsm_x4(a0h[0], a0h[1], a0h[2], a0h[3], xhB + aoff0 + ks * 32);
                ldsm_x4(a0l[0], a0l[1], a0l[2], a0l[3], xlB + aoff0 + ks * 32);
                ldsm_x4(a1h[0], a1h[1], a1h[2], a1h[3], xhB + aoff0 + 2304 + ks * 32);
                ldsm_x4(a1l[0], a1l[1], a1l[2], a1l[3], xlB + aoff0 + 2304 + ks * 32);
#pragma unroll
                for (int c3 = 0; c3 < 3; ++c3) {
                    const int chunk = nb + 4 * c3;
                    const unsigned kb = boff + (unsigned)(ks * 6400 + chunk * 32);
                    unsigned bh[4];
                    ldsm_x4t(bh[0], bh[1], bh[2], bh[3], whB + kb);
                    float* p00 = acc[0][c3 * 2];
                    float* p01 = acc[0][c3 * 2 + 1];
                    float* p10 = acc[1][c3 * 2];
                    float* p11 = acc[1][c3 * 2 + 1];
                    mma_f16(p00, a0h, bh[0], bh[1]);
                    mma_f16(p00, a0l, bh[0], bh[1]);
                    mma_f16(p01, a0h, bh[2], bh[3]);
                    mma_f16(p01, a0l, bh[2], bh[3]);
                    mma_f16(p10, a1h, bh[0], bh[1]);
                    mma_f16(p10, a1l, bh[0], bh[1]);
                    mma_f16(p11, a1h, bh[2], bh[3]);
                    mma_f16(p11, a1l, bh[2], bh[3]);
                }
            }
#pragma unroll
            for (int m = 0; m < 2; ++m) {
                const int crow = crow0 + m * 16;
#pragma unroll
                for (int c3 = 0; c3 < 3; ++c3) {
#pragma unroll
                    for (int nt = 0; nt < 2; ++nt) {
                        const int n0 = (nb + 4 * c3) * 16 + nt * 8;
                        const float* a = acc[m][c3 * 2 + nt];
                        const int i0 = crow * 100 + (n0 + ccol) / 2;
                        Hb32[i0]       = pack_h2(a[0], a[1]);
                        Hb32[i0 + 800] = pack_h2(a[2], a[3]);   // +8 rows
                    }
                }
            }
        }
        __syncthreads();

        // --- STS X(next 2t) (Xbuf free now) ---
        if (it2 < 5) {
#pragma unroll
            for (int q = 0; q < 4; ++q) {
                int e = tid + q * 256;
                if (q == 3 && tid >= 32) break;
                float4 v = (q == 0) ? px0 : (q == 1) ? px1 : (q == 2) ? px2 : px3;
                int tile = e / 400, er = e % 400;
                int r = (er >> 4) + tile * 32, c = (er & 15) * 4;
                unsigned h0, l0, h1, l1;
                split2h(v.x, v.y, h0, l0);
                split2h(v.z, v.w, h1, l1);
                *(uint2*)&Xh[r * 72 + c] = make_uint2(h0, h1);
                *(uint2*)&Xl[r * 72 + c] = make_uint2(l0, l1);
            }
        }

        // --- Y = (Ath+Atl)*Hh for both t's; At fragments shared ---
        {
            float Yacc[2][2][4];
#pragma unroll
            for (int tt = 0; tt < 2; ++tt)
#pragma unroll
                for (int tn = 0; tn < 2; ++tn)
#pragma unroll
                    for (int j = 0; j < 4; ++j) Yacc[tt][tn][j] = ybr[tn][j];

#pragma unroll
            for (int k = 0; k < 3; ++k) {
#pragma unroll
                for (int ks = 0; ks < 2; ++ks) {
                    const unsigned qa = (unsigned)(k * 2560 + mY * 1280 + ks * 32) + aoffY;
                    unsigned ah[4], al[4];
                    ldsm_x4(ah[0], ah[1], ah[2], ah[3], athB + qa);
                    ldsm_x4(al[0], al[1], al[2], al[3], atlB + qa);
#pragma unroll
                    for (int tt = 0; tt < 2; ++tt) {
                        const unsigned kb = (unsigned)((32 * tt + ks * 16) * 400 + k * 128 + nq * 32) + boffY;
                        unsigned bh[4];
                        ldsm_x4t(bh[0], bh[1], bh[2], bh[3], hbB + kb);
                        mma_f16(Yacc[tt][0], ah, bh[0], bh[1]);
                        mma_f16(Yacc[tt][0], al, bh[0], bh[1]);
                        mma_f16(Yacc[tt][1], ah, bh[2], bh[3]);
                        mma_f16(Yacc[tt][1], al, bh[2], bh[3]);
                    }
                }
            }
#pragma unroll
            for (int tt = 0; tt < 2; ++tt) {
                float* yout = y + (n * 300 + t0 + tt) * 1600;
#pragma unroll
                for (int tn = 0; tn < 2; ++tn) {
                    int f = f0 + tn * 8;
                    if (w0 < 25) *(float2*)&yout[w0 * 64 + f] = make_float2(Yacc[tt][tn][0], Yacc[tt][tn][1]);
                    if (w1 < 25) *(float2*)&yout[w1 * 64 + f] = make_float2(Yacc[tt][tn][2], Yacc[tt][tn][3]);
                }
            }
        }
        __syncthreads();
    }
}

// ---------------------------------------------------------------------------
extern "C" void kernel_launch(void* const* d_in, const int* in_sizes, int n_in,
                              void* d_out, int out_size)
{
    const float* x  = (const float*)d_in[0];
    const float* A  = (const float*)d_in[1];
    const float* W  = (const float*)d_in[2];
    const float* b  = (const float*)d_in[3];
    const float* Wq = (const float*)d_in[4];
    const float* bq = (const float*)d_in[5];
    const float* Wk = (const float*)d_in[6];
    const float* bk = (const float*)d_in[7];
    float* y = (float*)d_out;

    cudaFuncSetAttribute(score_kernel, cudaFuncAttributeMaxDynamicSharedMemorySize, SC_TOTAL);
    cudaFuncSetAttribute(main_kernel,  cudaFuncAttributeMaxDynamicSharedMemorySize, M_TOT);

    prep_kernel<<<48, 256>>>(W, Wq, Wk);
    score_kernel<<<dim3(30, 64), 256, SC_TOTAL>>>(x, bq, bk);
    softmax_kernel<<<192, 128>>>(A);
    main_kernel<<<dim3(25, 64), 256, M_TOT>>>(x, b, y);
}